// round 1
// baseline (speedup 1.0000x reference)
#include <cuda_runtime.h>
#include <math.h>

#define BB 32
#define NN 512
#define FIN 128
#define HID 32
#define NH 4
#define FOUT 128
#define NW (NN/32)   // 16 mask words per row

// ------------------------- scratch (device globals; no allocation) -------------------------
__device__ float    g_h0[(size_t)BB*NN*FIN];
__device__ float    g_s0[BB*NH*NN];
__device__ float    g_d0[BB*NH*NN];
__device__ float    g_m0[(size_t)BB*NN*FIN];   // elu(gat0 out)
__device__ float    g_h1[(size_t)BB*NN*FOUT];
__device__ float    g_s1[BB*NN];
__device__ float    g_d1[BB*NN];
__device__ float    g_m1[(size_t)BB*NN*FOUT];  // gat1 out
__device__ unsigned g_mask[BB*NN*NW];

// ------------------------- helpers -------------------------
__device__ __forceinline__ float qsum(float v) {
    v += __shfl_xor_sync(0xffffffffu, v, 1);
    v += __shfl_xor_sync(0xffffffffu, v, 2);
    return v;
}
__device__ __forceinline__ float lrelu(float z) { return z > 0.0f ? z : 0.2f * z; }
__device__ __forceinline__ float gelu_exact(float v) {
    return 0.5f * v * (1.0f + erff(v * 0.70710678118654752f));
}

// swizzled stage of a 32x128 weight tile: W[(kt*32+f)*128+o] -> ws[f*128 + pos(o)]
// pos(o) with o = chunk*32 + d:  (d>>2)*16 + chunk*4 + (d&3)
// read side: float4 at (float4*)(ws+f*128)[d4*4 + chunk]  -> conflict-free
__device__ __forceinline__ void stage_w(const float* __restrict__ W, float* ws, int kt, int t) {
    for (int i = t; i < 32 * 128; i += 256) {
        int f = i >> 7, o = i & 127;
        ws[f * 128 + ((o & 31) >> 2) * 16 + (o >> 5) * 4 + (o & 3)] = W[(kt * 32 + f) * 128 + o];
    }
}

// acc[32] += src_row @ W   (K = K32*32, src row at src[nl*sstride + k])
__device__ __forceinline__ void mm_acc(const float* __restrict__ W, const float* src, int sstride,
                                       float* ws, float acc[32], int K32, int c, int nl, int t) {
    for (int kt = 0; kt < K32; kt++) {
        __syncthreads();
        stage_w(W, ws, kt, t);
        __syncthreads();
#pragma unroll 4
        for (int f = 0; f < 32; f++) {
            float tv = src[nl * sstride + kt * 32 + f];
            const float4* wr = (const float4*)(ws + f * 128);
#pragma unroll
            for (int d4 = 0; d4 < 8; d4++) {
                float4 w4 = wr[d4 * 4 + c];
                acc[4 * d4 + 0] += tv * w4.x;
                acc[4 * d4 + 1] += tv * w4.y;
                acc[4 * d4 + 2] += tv * w4.z;
                acc[4 * d4 + 3] += tv * w4.w;
            }
        }
    }
}

// ------------------------- kernel: adjacency -> bitmask -------------------------
__global__ void k_mask(const int* __restrict__ graph) {
    int idx = blockIdx.x * 256 + threadIdx.x;        // over B*N*N
    int m = idx & (NN - 1);
    int n = (idx >> 9) & (NN - 1);
    bool pred = (graph[idx] > 0) || (m == n);
    unsigned w = __ballot_sync(0xffffffffu, pred);
    if ((m & 31) == 0) g_mask[idx >> 5] = w;
}

// ------------------------- kernel: GAT0 projection h0 = x@W0, s0, d0 -------------------------
__global__ void k_proj0(const float* __restrict__ x, const float* __restrict__ W,
                        const float* __restrict__ asrc, const float* __restrict__ adst) {
    __shared__ float xs[128 * 33];
    __shared__ float ws[32 * 128];
    int b = blockIdx.y, nb = blockIdx.x * 128;
    int t = threadIdx.x, c = t & 3, rp = t >> 2;
    int n0 = 2 * rp, n1 = n0 + 1;
    float a0[32], a1[32];
#pragma unroll
    for (int d = 0; d < 32; d++) { a0[d] = 0.0f; a1[d] = 0.0f; }
    const float* xb = x + ((size_t)b * NN + nb) * FIN;

    for (int kt = 0; kt < 4; kt++) {
        __syncthreads();
        for (int i = t; i < 128 * 32; i += 256) {
            int n = i >> 5, f = i & 31;
            xs[n * 33 + f] = xb[n * FIN + kt * 32 + f];
        }
        stage_w(W, ws, kt, t);
        __syncthreads();
#pragma unroll 4
        for (int f = 0; f < 32; f++) {
            float x0 = xs[n0 * 33 + f], x1 = xs[n1 * 33 + f];
            const float4* wr = (const float4*)(ws + f * 128);
#pragma unroll
            for (int d4 = 0; d4 < 8; d4++) {
                float4 w4 = wr[d4 * 4 + c];
                a0[4 * d4 + 0] += x0 * w4.x; a0[4 * d4 + 1] += x0 * w4.y;
                a0[4 * d4 + 2] += x0 * w4.z; a0[4 * d4 + 3] += x0 * w4.w;
                a1[4 * d4 + 0] += x1 * w4.x; a1[4 * d4 + 1] += x1 * w4.y;
                a1[4 * d4 + 2] += x1 * w4.z; a1[4 * d4 + 3] += x1 * w4.w;
            }
        }
    }
    float* hp = g_h0 + ((size_t)b * NN + nb) * FIN;
#pragma unroll
    for (int d4 = 0; d4 < 8; d4++) {
        ((float4*)(hp + n0 * FIN + c * 32))[d4] =
            make_float4(a0[4 * d4], a0[4 * d4 + 1], a0[4 * d4 + 2], a0[4 * d4 + 3]);
        ((float4*)(hp + n1 * FIN + c * 32))[d4] =
            make_float4(a1[4 * d4], a1[4 * d4 + 1], a1[4 * d4 + 2], a1[4 * d4 + 3]);
    }
    float s0v = 0, d0v = 0, s1v = 0, d1v = 0;
#pragma unroll
    for (int d = 0; d < 32; d++) {
        float av = asrc[c * 32 + d], bv = adst[c * 32 + d];
        s0v += a0[d] * av; d0v += a0[d] * bv;
        s1v += a1[d] * av; d1v += a1[d] * bv;
    }
    g_s0[(b * NH + c) * NN + nb + n0] = s0v;
    g_d0[(b * NH + c) * NN + nb + n0] = d0v;
    g_s0[(b * NH + c) * NN + nb + n1] = s1v;
    g_d0[(b * NH + c) * NN + nb + n1] = d1v;
}

// ------------------------- kernel: GAT1 projection h1 = m0@W1, s1, d1 -------------------------
__global__ void k_proj1(const float* __restrict__ W, const float* __restrict__ asrc,
                        const float* __restrict__ adst) {
    __shared__ float xs[128 * 33];
    __shared__ float ws[32 * 128];
    int b = blockIdx.y, nb = blockIdx.x * 128;
    int t = threadIdx.x, c = t & 3, rp = t >> 2;
    int n0 = 2 * rp, n1 = n0 + 1;
    float a0[32], a1[32];
#pragma unroll
    for (int d = 0; d < 32; d++) { a0[d] = 0.0f; a1[d] = 0.0f; }
    const float* xb = g_m0 + ((size_t)b * NN + nb) * FIN;

    for (int kt = 0; kt < 4; kt++) {
        __syncthreads();
        for (int i = t; i < 128 * 32; i += 256) {
            int n = i >> 5, f = i & 31;
            xs[n * 33 + f] = xb[n * FIN + kt * 32 + f];
        }
        stage_w(W, ws, kt, t);
        __syncthreads();
#pragma unroll 4
        for (int f = 0; f < 32; f++) {
            float x0 = xs[n0 * 33 + f], x1 = xs[n1 * 33 + f];
            const float4* wr = (const float4*)(ws + f * 128);
#pragma unroll
            for (int d4 = 0; d4 < 8; d4++) {
                float4 w4 = wr[d4 * 4 + c];
                a0[4 * d4 + 0] += x0 * w4.x; a0[4 * d4 + 1] += x0 * w4.y;
                a0[4 * d4 + 2] += x0 * w4.z; a0[4 * d4 + 3] += x0 * w4.w;
                a1[4 * d4 + 0] += x1 * w4.x; a1[4 * d4 + 1] += x1 * w4.y;
                a1[4 * d4 + 2] += x1 * w4.z; a1[4 * d4 + 3] += x1 * w4.w;
            }
        }
    }
    float* hp = g_h1 + ((size_t)b * NN + nb) * FOUT;
#pragma unroll
    for (int d4 = 0; d4 < 8; d4++) {
        ((float4*)(hp + n0 * FOUT + c * 32))[d4] =
            make_float4(a0[4 * d4], a0[4 * d4 + 1], a0[4 * d4 + 2], a0[4 * d4 + 3]);
        ((float4*)(hp + n1 * FOUT + c * 32))[d4] =
            make_float4(a1[4 * d4], a1[4 * d4 + 1], a1[4 * d4 + 2], a1[4 * d4 + 3]);
    }
    float s0p = 0, d0p = 0, s1p = 0, d1p = 0;
#pragma unroll
    for (int d = 0; d < 32; d++) {
        float av = asrc[c * 32 + d], bv = adst[c * 32 + d];
        s0p += a0[d] * av; d0p += a0[d] * bv;
        s1p += a1[d] * av; d1p += a1[d] * bv;
    }
    s0p = qsum(s0p); d0p = qsum(d0p);
    s1p = qsum(s1p); d1p = qsum(d1p);
    if (c == 0) {
        g_s1[b * NN + nb + n0] = s0p; g_d1[b * NN + nb + n0] = d0p;
        g_s1[b * NN + nb + n1] = s1p; g_d1[b * NN + nb + n1] = d1p;
    }
}

// ------------------------- kernel: GAT0 masked softmax + aggregation + ELU -------------------------
__global__ void k_attn0() {
    __shared__ float d0s[NH * 513];
    __shared__ unsigned mk[64 * NW];
    __shared__ float hs[64 * 128];
    int b = blockIdx.y, nb = blockIdx.x * 64;
    int t = threadIdx.x, h = t & 3, nl = t >> 2;

    for (int i = t; i < NH * NN; i += 256) {
        int hh = i >> 9, m = i & 511;
        d0s[hh * 513 + m] = g_d0[(b * NH + hh) * NN + m];
    }
    for (int i = t; i < 64 * NW; i += 256)
        mk[i] = g_mask[(b * NN + nb) * NW + i];
    __syncthreads();

    float s = g_s0[(b * NH + h) * NN + nb + nl];

    // pass 1: masked max
    float M = -1e30f;
    for (int mb = 0; mb < NW; mb++) {
        unsigned bits = mk[nl * NW + mb];
#pragma unroll 8
        for (int j = 0; j < 32; j++) {
            float z = lrelu(s + d0s[h * 513 + mb * 32 + j]);
            if ((bits >> j) & 1u) M = fmaxf(M, z);
        }
    }

    // pass 2: aggregation (sum of weights folded in)
    float acc[32];
#pragma unroll
    for (int d = 0; d < 32; d++) acc[d] = 0.0f;
    float S = 0.0f;

    for (int mt = 0; mt < 8; mt++) {
        __syncthreads();
        for (int i = t; i < 64 * 128; i += 256) {
            int mr = i >> 7, o = i & 127;
            hs[mr * 128 + ((o & 31) >> 2) * 16 + (o >> 5) * 4 + (o & 3)] =
                g_h0[((size_t)b * NN + mt * 64 + mr) * FIN + o];
        }
        __syncthreads();
        for (int mb = 0; mb < 2; mb++) {
            unsigned bits = mk[nl * NW + mt * 2 + mb];
            for (int j = 0; j < 32; j++) {
                int mm = mb * 32 + j;
                float z = lrelu(s + d0s[h * 513 + mt * 64 + mm]);
                float w = __expf(z - M) * (float)((bits >> j) & 1u);
                S += w;
                const float4* hr = (const float4*)(hs + mm * 128);
#pragma unroll
                for (int d4 = 0; d4 < 8; d4++) {
                    float4 h4 = hr[d4 * 4 + h];
                    acc[4 * d4 + 0] += w * h4.x; acc[4 * d4 + 1] += w * h4.y;
                    acc[4 * d4 + 2] += w * h4.z; acc[4 * d4 + 3] += w * h4.w;
                }
            }
        }
    }
    float inv = 1.0f / S;
    float* mp = g_m0 + ((size_t)b * NN + nb + nl) * FIN + h * 32;
#pragma unroll
    for (int d4 = 0; d4 < 8; d4++) {
        float v0 = acc[4 * d4 + 0] * inv, v1 = acc[4 * d4 + 1] * inv;
        float v2 = acc[4 * d4 + 2] * inv, v3 = acc[4 * d4 + 3] * inv;
        v0 = v0 > 0.0f ? v0 : expm1f(v0);
        v1 = v1 > 0.0f ? v1 : expm1f(v1);
        v2 = v2 > 0.0f ? v2 : expm1f(v2);
        v3 = v3 > 0.0f ? v3 : expm1f(v3);
        ((float4*)mp)[d4] = make_float4(v0, v1, v2, v3);
    }
}

// ------------------------- kernel: GAT1 masked softmax + aggregation -------------------------
__global__ void k_attn1() {
    __shared__ float d1s[NN];
    __shared__ unsigned mk[64 * NW];
    __shared__ float hs[64 * 128];
    int b = blockIdx.y, nb = blockIdx.x * 64;
    int t = threadIdx.x, c = t & 3, nl = t >> 2;

    for (int i = t; i < NN; i += 256) d1s[i] = g_d1[b * NN + i];
    for (int i = t; i < 64 * NW; i += 256)
        mk[i] = g_mask[(b * NN + nb) * NW + i];
    __syncthreads();

    float s = g_s1[b * NN + nb + nl];

    float M = -1e30f;
    for (int mb = 0; mb < NW; mb++) {
        unsigned bits = mk[nl * NW + mb];
#pragma unroll 8
        for (int j = 0; j < 32; j++) {
            float z = lrelu(s + d1s[mb * 32 + j]);
            if ((bits >> j) & 1u) M = fmaxf(M, z);
        }
    }

    float acc[32];
#pragma unroll
    for (int d = 0; d < 32; d++) acc[d] = 0.0f;
    float S = 0.0f;

    for (int mt = 0; mt < 8; mt++) {
        __syncthreads();
        for (int i = t; i < 64 * 128; i += 256) {
            int mr = i >> 7, o = i & 127;
            hs[mr * 128 + ((o & 31) >> 2) * 16 + (o >> 5) * 4 + (o & 3)] =
                g_h1[((size_t)b * NN + mt * 64 + mr) * FOUT + o];
        }
        __syncthreads();
        for (int mb = 0; mb < 2; mb++) {
            unsigned bits = mk[nl * NW + mt * 2 + mb];
            for (int j = 0; j < 32; j++) {
                int mm = mb * 32 + j;
                float z = lrelu(s + d1s[mt * 64 + mm]);
                float w = __expf(z - M) * (float)((bits >> j) & 1u);
                S += w;
                const float4* hr = (const float4*)(hs + mm * 128);
#pragma unroll
                for (int d4 = 0; d4 < 8; d4++) {
                    float4 h4 = hr[d4 * 4 + c];
                    acc[4 * d4 + 0] += w * h4.x; acc[4 * d4 + 1] += w * h4.y;
                    acc[4 * d4 + 2] += w * h4.z; acc[4 * d4 + 3] += w * h4.w;
                }
            }
        }
    }
    float inv = 1.0f / S;
    float* mp = g_m1 + ((size_t)b * NN + nb + nl) * FOUT + c * 32;
#pragma unroll
    for (int d4 = 0; d4 < 8; d4++) {
        ((float4*)mp)[d4] = make_float4(acc[4 * d4] * inv, acc[4 * d4 + 1] * inv,
                                        acc[4 * d4 + 2] * inv, acc[4 * d4 + 3] * inv);
    }
}

// ------------------------- kernel: fused tail -------------------------
#define TS_STRIDE 260
#define MS_STRIDE 132
#define TAIL_SMEM ((64 * TS_STRIDE + 2 * 64 * MS_STRIDE + 32 * 128) * 4)

__global__ void k_tail(const float* __restrict__ x,
                       const float* __restrict__ ln1g, const float* __restrict__ ln1b,
                       const float* __restrict__ linW, const float* __restrict__ linb,
                       const float* __restrict__ meW0, const float* __restrict__ meb0,
                       const float* __restrict__ meW1, const float* __restrict__ meb1,
                       const float* __restrict__ ln2g, const float* __restrict__ ln2b,
                       const float* __restrict__ ohW, const float* __restrict__ ohb,
                       const float* __restrict__ ln3g, const float* __restrict__ ln3b,
                       float* __restrict__ out) {
    extern __shared__ float sm[];
    float* ts = sm;                      // 64 x 260 (concat vec, then LN1 result)
    float* ms = ts + 64 * TS_STRIDE;     // 64 x 132 (post-linear m)
    float* us = ms + 64 * MS_STRIDE;     // 64 x 132 (gelu mid / ln2 out)
    float* ws = us + 64 * MS_STRIDE;     // 32 x 128 staged weight tile

    int b = blockIdx.y, nb = blockIdx.x * 64;
    int t = threadIdx.x, c = t & 3, nl = t >> 2;
    int n = nb + nl;

    // load concat [x | m1] cooperatively
    for (int i = t; i < 64 * 256; i += 256) {
        int r = i >> 8, j = i & 255;
        size_t row = (size_t)b * NN + nb + r;
        float v = (j < 128) ? x[row * FIN + j] : g_m1[row * FOUT + (j - 128)];
        ts[r * TS_STRIDE + j] = v;
    }
    __syncthreads();

    // LN1 over 256
    float sum = 0, sq = 0;
#pragma unroll 8
    for (int i = 0; i < 64; i++) {
        float v = ts[nl * TS_STRIDE + c * 64 + i];
        sum += v; sq += v * v;
    }
    sum = qsum(sum); sq = qsum(sq);
    float mu = sum * (1.0f / 256.0f);
    float rstd = rsqrtf(sq * (1.0f / 256.0f) - mu * mu + 1e-5f);
#pragma unroll 8
    for (int i = 0; i < 64; i++) {
        int j = c * 64 + i;
        float v = ts[nl * TS_STRIDE + j];
        ts[nl * TS_STRIDE + j] = (v - mu) * rstd * ln1g[j] + ln1b[j];
    }
    // no sync needed: same thread-quad owns the row it reads later? NO — matmul
    // reads ts[nl][k] for ALL k; mm_acc's first __syncthreads() orders it.

    // matmul 1: m = LN1 @ linW + linb
    float mreg[32];
#pragma unroll
    for (int d = 0; d < 32; d++) mreg[d] = 0.0f;
    mm_acc(linW, ts, TS_STRIDE, ws, mreg, 8, c, nl, t);
#pragma unroll
    for (int d = 0; d < 32; d++) {
        mreg[d] += linb[c * 32 + d];
        ms[nl * MS_STRIDE + c * 32 + d] = mreg[d];
    }

    // matmul 2: g = gelu(m @ meW0 + meb0)
    float a2[32];
#pragma unroll
    for (int d = 0; d < 32; d++) a2[d] = 0.0f;
    mm_acc(meW0, ms, MS_STRIDE, ws, a2, 4, c, nl, t);
#pragma unroll
    for (int d = 0; d < 32; d++)
        us[nl * MS_STRIDE + c * 32 + d] = gelu_exact(a2[d] + meb0[c * 32 + d]);

    // matmul 3: enc = g @ meW1 + meb1 ; r = m + enc ; LN2
    float a3[32];
#pragma unroll
    for (int d = 0; d < 32; d++) a3[d] = 0.0f;
    mm_acc(meW1, us, MS_STRIDE, ws, a3, 4, c, nl, t);
    sum = 0; sq = 0;
#pragma unroll
    for (int d = 0; d < 32; d++) {
        a3[d] = a3[d] + meb1[c * 32 + d] + mreg[d];
        sum += a3[d]; sq += a3[d] * a3[d];
    }
    sum = qsum(sum); sq = qsum(sq);
    mu = sum * (1.0f / 128.0f);
    rstd = rsqrtf(sq * (1.0f / 128.0f) - mu * mu + 1e-5f);
    __syncthreads();   // all reads of us in matmul 3 done before overwrite
#pragma unroll
    for (int d = 0; d < 32; d++) {
        int o = c * 32 + d;
        us[nl * MS_STRIDE + o] = (a3[d] - mu) * rstd * ln2g[o] + ln2b[o];
    }

    // matmul 4: v = gelu(u @ ohW + ohb) ; LN3 ; write out
    float a4[32];
#pragma unroll
    for (int d = 0; d < 32; d++) a4[d] = 0.0f;
    mm_acc(ohW, us, MS_STRIDE, ws, a4, 4, c, nl, t);
    sum = 0; sq = 0;
#pragma unroll
    for (int d = 0; d < 32; d++) {
        float v = gelu_exact(a4[d] + ohb[c * 32 + d]);
        a4[d] = v;
        sum += v; sq += v * v;
    }
    sum = qsum(sum); sq = qsum(sq);
    mu = sum * (1.0f / 128.0f);
    rstd = rsqrtf(sq * (1.0f / 128.0f) - mu * mu + 1e-5f);

    float* op = out + ((size_t)b * NN + n) * FOUT + c * 32;
#pragma unroll
    for (int d4 = 0; d4 < 8; d4++) {
        float r0 = (a4[4 * d4 + 0] - mu) * rstd * ln3g[c * 32 + 4 * d4 + 0] + ln3b[c * 32 + 4 * d4 + 0];
        float r1 = (a4[4 * d4 + 1] - mu) * rstd * ln3g[c * 32 + 4 * d4 + 1] + ln3b[c * 32 + 4 * d4 + 1];
        float r2 = (a4[4 * d4 + 2] - mu) * rstd * ln3g[c * 32 + 4 * d4 + 2] + ln3b[c * 32 + 4 * d4 + 2];
        float r3 = (a4[4 * d4 + 3] - mu) * rstd * ln3g[c * 32 + 4 * d4 + 3] + ln3b[c * 32 + 4 * d4 + 3];
        ((float4*)op)[d4] = make_float4(r0, r1, r2, r3);
    }
}

// ------------------------- launch -------------------------
extern "C" void kernel_launch(void* const* d_in, const int* in_sizes, int n_in,
                              void* d_out, int out_size) {
    const float* x    = (const float*)d_in[0];
    const int*   grp  = (const int*)  d_in[1];
    const float* W0   = (const float*)d_in[2];
    const float* as0  = (const float*)d_in[3];
    const float* ad0  = (const float*)d_in[4];
    const float* W1   = (const float*)d_in[5];
    const float* as1  = (const float*)d_in[6];
    const float* ad1  = (const float*)d_in[7];
    const float* ln1g = (const float*)d_in[8];
    const float* ln1b = (const float*)d_in[9];
    const float* linW = (const float*)d_in[10];
    const float* linb = (const float*)d_in[11];
    const float* meW0 = (const float*)d_in[12];
    const float* meb0 = (const float*)d_in[13];
    const float* meW1 = (const float*)d_in[14];
    const float* meb1 = (const float*)d_in[15];
    const float* ln2g = (const float*)d_in[16];
    const float* ln2b = (const float*)d_in[17];
    const float* ohW  = (const float*)d_in[18];
    const float* ohb  = (const float*)d_in[19];
    const float* ln3g = (const float*)d_in[20];
    const float* ln3b = (const float*)d_in[21];
    float* out = (float*)d_out;

    cudaFuncSetAttribute(k_tail, cudaFuncAttributeMaxDynamicSharedMemorySize, TAIL_SMEM);

    k_mask<<<(BB * NN * NN) / 256, 256>>>(grp);
    k_proj0<<<dim3(NN / 128, BB), 256>>>(x, W0, as0, ad0);
    k_attn0<<<dim3(NN / 64, BB), 256>>>();
    k_proj1<<<dim3(NN / 128, BB), 256>>>(W1, as1, ad1);
    k_attn1<<<dim3(NN / 64, BB), 256>>>();
    k_tail<<<dim3(NN / 64, BB), 256, TAIL_SMEM>>>(x, ln1g, ln1b, linW, linb,
                                                  meW0, meb0, meW1, meb1,
                                                  ln2g, ln2b, ohb ? ohW : ohW, ohb,
                                                  ln3g, ln3b, out);
}

// round 2
// speedup vs baseline: 2.4318x; 2.4318x over previous
#include <cuda_runtime.h>
#include <math.h>

#define BB 32
#define NN 512
#define FIN 128
#define HID 32
#define NH 4
#define FOUT 128
#define NW (NN/32)   // 16 mask words per row

// ------------------------- scratch (device globals; no allocation) -------------------------
__device__ float    g_h0[(size_t)BB*NN*FIN];
__device__ float    g_s0[BB*NH*NN];
__device__ float    g_d0[BB*NH*NN];
__device__ float    g_m0[(size_t)BB*NN*FIN];   // elu(gat0 out)
__device__ float    g_h1[(size_t)BB*NN*FOUT];
__device__ float    g_s1[BB*NN];
__device__ float    g_d1[BB*NN];
__device__ float    g_m1[(size_t)BB*NN*FOUT];  // gat1 out
__device__ unsigned g_mask[BB*NN*NW];

// ------------------------- helpers -------------------------
__device__ __forceinline__ float qsum(float v) {
    v += __shfl_xor_sync(0xffffffffu, v, 1);
    v += __shfl_xor_sync(0xffffffffu, v, 2);
    return v;
}
__device__ __forceinline__ float lrelu(float z) { return z > 0.0f ? z : 0.2f * z; }
__device__ __forceinline__ float gelu_exact(float v) {
    return 0.5f * v * (1.0f + erff(v * 0.70710678118654752f));
}
__device__ __forceinline__ unsigned f2tf(float f) {
    unsigned u; asm("cvt.rna.tf32.f32 %0, %1;" : "=r"(u) : "f"(f)); return u;
}
__device__ __forceinline__ void mma_tf32(float c[4], const unsigned a[4], const unsigned b[2]) {
    asm volatile("mma.sync.aligned.m16n8k8.row.col.f32.tf32.tf32.f32 "
                 "{%0,%1,%2,%3}, {%4,%5,%6,%7}, {%8,%9}, {%0,%1,%2,%3};"
                 : "+f"(c[0]), "+f"(c[1]), "+f"(c[2]), "+f"(c[3])
                 : "r"(a[0]), "r"(a[1]), "r"(a[2]), "r"(a[3]), "r"(b[0]), "r"(b[1]));
}

// swizzled stage of a 32x128 weight tile (scalar GEMM path)
__device__ __forceinline__ void stage_w(const float* __restrict__ W, float* ws, int kt, int t) {
    for (int i = t; i < 32 * 128; i += 256) {
        int f = i >> 7, o = i & 127;
        ws[f * 128 + ((o & 31) >> 2) * 16 + (o >> 5) * 4 + (o & 3)] = W[(kt * 32 + f) * 128 + o];
    }
}

__device__ __forceinline__ void mm_acc(const float* __restrict__ W, const float* src, int sstride,
                                       float* ws, float acc[32], int K32, int c, int nl, int t) {
    for (int kt = 0; kt < K32; kt++) {
        __syncthreads();
        stage_w(W, ws, kt, t);
        __syncthreads();
#pragma unroll 4
        for (int f = 0; f < 32; f++) {
            float tv = src[nl * sstride + kt * 32 + f];
            const float4* wr = (const float4*)(ws + f * 128);
#pragma unroll
            for (int d4 = 0; d4 < 8; d4++) {
                float4 w4 = wr[d4 * 4 + c];
                acc[4 * d4 + 0] += tv * w4.x;
                acc[4 * d4 + 1] += tv * w4.y;
                acc[4 * d4 + 2] += tv * w4.z;
                acc[4 * d4 + 3] += tv * w4.w;
            }
        }
    }
}

// ------------------------- kernel: adjacency -> bitmask -------------------------
__global__ void k_mask(const int* __restrict__ graph) {
    int idx = blockIdx.x * 256 + threadIdx.x;
    int m = idx & (NN - 1);
    int n = (idx >> 9) & (NN - 1);
    bool pred = (graph[idx] > 0) || (m == n);
    unsigned w = __ballot_sync(0xffffffffu, pred);
    if ((m & 31) == 0) g_mask[idx >> 5] = w;
}

// ------------------------- kernel: GAT0 projection -------------------------
__global__ void k_proj0(const float* __restrict__ x, const float* __restrict__ W,
                        const float* __restrict__ asrc, const float* __restrict__ adst) {
    __shared__ float xs[128 * 33];
    __shared__ float ws[32 * 128];
    int b = blockIdx.y, nb = blockIdx.x * 128;
    int t = threadIdx.x, c = t & 3, rp = t >> 2;
    int n0 = 2 * rp, n1 = n0 + 1;
    float a0[32], a1[32];
#pragma unroll
    for (int d = 0; d < 32; d++) { a0[d] = 0.0f; a1[d] = 0.0f; }
    const float* xb = x + ((size_t)b * NN + nb) * FIN;

    for (int kt = 0; kt < 4; kt++) {
        __syncthreads();
        for (int i = t; i < 128 * 32; i += 256) {
            int n = i >> 5, f = i & 31;
            xs[n * 33 + f] = xb[n * FIN + kt * 32 + f];
        }
        stage_w(W, ws, kt, t);
        __syncthreads();
#pragma unroll 4
        for (int f = 0; f < 32; f++) {
            float x0 = xs[n0 * 33 + f], x1 = xs[n1 * 33 + f];
            const float4* wr = (const float4*)(ws + f * 128);
#pragma unroll
            for (int d4 = 0; d4 < 8; d4++) {
                float4 w4 = wr[d4 * 4 + c];
                a0[4 * d4 + 0] += x0 * w4.x; a0[4 * d4 + 1] += x0 * w4.y;
                a0[4 * d4 + 2] += x0 * w4.z; a0[4 * d4 + 3] += x0 * w4.w;
                a1[4 * d4 + 0] += x1 * w4.x; a1[4 * d4 + 1] += x1 * w4.y;
                a1[4 * d4 + 2] += x1 * w4.z; a1[4 * d4 + 3] += x1 * w4.w;
            }
        }
    }
    float* hp = g_h0 + ((size_t)b * NN + nb) * FIN;
#pragma unroll
    for (int d4 = 0; d4 < 8; d4++) {
        ((float4*)(hp + n0 * FIN + c * 32))[d4] =
            make_float4(a0[4 * d4], a0[4 * d4 + 1], a0[4 * d4 + 2], a0[4 * d4 + 3]);
        ((float4*)(hp + n1 * FIN + c * 32))[d4] =
            make_float4(a1[4 * d4], a1[4 * d4 + 1], a1[4 * d4 + 2], a1[4 * d4 + 3]);
    }
    float s0v = 0, d0v = 0, s1v = 0, d1v = 0;
#pragma unroll
    for (int d = 0; d < 32; d++) {
        float av = asrc[c * 32 + d], bv = adst[c * 32 + d];
        s0v += a0[d] * av; d0v += a0[d] * bv;
        s1v += a1[d] * av; d1v += a1[d] * bv;
    }
    g_s0[(b * NH + c) * NN + nb + n0] = s0v;
    g_d0[(b * NH + c) * NN + nb + n0] = d0v;
    g_s0[(b * NH + c) * NN + nb + n1] = s1v;
    g_d0[(b * NH + c) * NN + nb + n1] = d1v;
}

// ------------------------- kernel: GAT1 projection -------------------------
__global__ void k_proj1(const float* __restrict__ W, const float* __restrict__ asrc,
                        const float* __restrict__ adst) {
    __shared__ float xs[128 * 33];
    __shared__ float ws[32 * 128];
    int b = blockIdx.y, nb = blockIdx.x * 128;
    int t = threadIdx.x, c = t & 3, rp = t >> 2;
    int n0 = 2 * rp, n1 = n0 + 1;
    float a0[32], a1[32];
#pragma unroll
    for (int d = 0; d < 32; d++) { a0[d] = 0.0f; a1[d] = 0.0f; }
    const float* xb = g_m0 + ((size_t)b * NN + nb) * FIN;

    for (int kt = 0; kt < 4; kt++) {
        __syncthreads();
        for (int i = t; i < 128 * 32; i += 256) {
            int n = i >> 5, f = i & 31;
            xs[n * 33 + f] = xb[n * FIN + kt * 32 + f];
        }
        stage_w(W, ws, kt, t);
        __syncthreads();
#pragma unroll 4
        for (int f = 0; f < 32; f++) {
            float x0 = xs[n0 * 33 + f], x1 = xs[n1 * 33 + f];
            const float4* wr = (const float4*)(ws + f * 128);
#pragma unroll
            for (int d4 = 0; d4 < 8; d4++) {
                float4 w4 = wr[d4 * 4 + c];
                a0[4 * d4 + 0] += x0 * w4.x; a0[4 * d4 + 1] += x0 * w4.y;
                a0[4 * d4 + 2] += x0 * w4.z; a0[4 * d4 + 3] += x0 * w4.w;
                a1[4 * d4 + 0] += x1 * w4.x; a1[4 * d4 + 1] += x1 * w4.y;
                a1[4 * d4 + 2] += x1 * w4.z; a1[4 * d4 + 3] += x1 * w4.w;
            }
        }
    }
    float* hp = g_h1 + ((size_t)b * NN + nb) * FOUT;
#pragma unroll
    for (int d4 = 0; d4 < 8; d4++) {
        ((float4*)(hp + n0 * FOUT + c * 32))[d4] =
            make_float4(a0[4 * d4], a0[4 * d4 + 1], a0[4 * d4 + 2], a0[4 * d4 + 3]);
        ((float4*)(hp + n1 * FOUT + c * 32))[d4] =
            make_float4(a1[4 * d4], a1[4 * d4 + 1], a1[4 * d4 + 2], a1[4 * d4 + 3]);
    }
    float s0p = 0, d0p = 0, s1p = 0, d1p = 0;
#pragma unroll
    for (int d = 0; d < 32; d++) {
        float av = asrc[c * 32 + d], bv = adst[c * 32 + d];
        s0p += a0[d] * av; d0p += a0[d] * bv;
        s1p += a1[d] * av; d1p += a1[d] * bv;
    }
    s0p = qsum(s0p); d0p = qsum(d0p);
    s1p = qsum(s1p); d1p = qsum(d1p);
    if (c == 0) {
        g_s1[b * NN + nb + n0] = s0p; g_d1[b * NN + nb + n0] = d0p;
        g_s1[b * NN + nb + n1] = s1p; g_d1[b * NN + nb + n1] = d1p;
    }
}

// ------------------------- attn0: tf32 mma flash-style, 4 heads, D=32 -------------------------
// CTA: 64 rows, 256 threads (8 warps). warp w: head h=w>>1, stripes (w&1) and (w&1)+2.
// smem floats: sP[4][64][66] | sH[64][128] swizzled | sd[4][512] | ss[4][64] | sS[4][64] | mk[64][16]
#define A0_SMEM ((4*64*66 + 64*128 + 4*512 + 4*64 + 4*64 + 64*16) * 4)

__global__ __launch_bounds__(256, 2) void k_attn0_mma() {
    extern __shared__ float sm[];
    float* sP = sm;
    float* sH = sP + 4 * 64 * 66;
    float* sd = sH + 64 * 128;
    float* ss = sd + 4 * 512;
    float* sS = ss + 4 * 64;
    unsigned* mk = (unsigned*)(sS + 4 * 64);

    int b = blockIdx.y, nb = blockIdx.x * 64;
    int t = threadIdx.x;
    int w = t >> 5, lane = t & 31;
    int g = lane >> 2, tg = lane & 3;

    for (int i = t; i < 4 * 512; i += 256) sd[i] = g_d0[b * NH * NN + i];
    for (int i = t; i < 4 * 64; i += 256) {
        int hh = i >> 6, n = i & 63;
        ss[i] = g_s0[(b * NH + hh) * NN + nb + n];
    }
    for (int i = t; i < 64 * NW; i += 256) mk[i] = g_mask[(b * NN + nb) * NW + i];
    __syncthreads();

    int ph = t >> 6, pn = t & 63;       // P-compute ownership: (head, row)
    float sval = ss[ph * 64 + pn];
    float Sreg = 0.0f;

    int h = w >> 1;
    int s0r = (w & 1) * 16;             // stripe row bases: s0r, s0r+32
    float c[2][4][4];
#pragma unroll
    for (int sp = 0; sp < 2; sp++)
#pragma unroll
        for (int j = 0; j < 4; j++)
#pragma unroll
            for (int e = 0; e < 4; e++) c[sp][j][e] = 0.0f;

    for (int mt = 0; mt < 8; mt++) {
        __syncthreads();
        // stage H chunk [64 x 128] (tf32, XOR-swizzled cols)
        for (int i = t; i < 64 * 32; i += 256) {
            int r = i >> 5, c4 = (i & 31) * 4;
            float4 v = *(const float4*)&g_h0[((size_t)b * NN + mt * 64 + r) * FIN + c4];
            int cs = c4 ^ ((r & 3) << 3);
            float4 o;
            o.x = __uint_as_float(f2tf(v.x)); o.y = __uint_as_float(f2tf(v.y));
            o.z = __uint_as_float(f2tf(v.z)); o.w = __uint_as_float(f2tf(v.w));
            *(float4*)&sH[r * 128 + cs] = o;
        }
        // compute P chunk [4][64 rows][64 m]
        {
            unsigned bits0 = mk[pn * NW + mt * 2];
            unsigned bits1 = mk[pn * NW + mt * 2 + 1];
            const float* dp = sd + ph * 512 + mt * 64;
            float* pp = sP + (ph * 64 + pn) * 66;
#pragma unroll 8
            for (int m = 0; m < 32; m++) {
                float z = lrelu(sval + dp[m]);
                float wg = ((bits0 >> m) & 1u) ? __expf(z) : 0.0f;
                Sreg += wg;
                pp[m] = __uint_as_float(f2tf(wg));
            }
#pragma unroll 8
            for (int m = 0; m < 32; m++) {
                float z = lrelu(sval + dp[32 + m]);
                float wg = ((bits1 >> m) & 1u) ? __expf(z) : 0.0f;
                Sreg += wg;
                pp[32 + m] = __uint_as_float(f2tf(wg));
            }
        }
        __syncthreads();
        // mma over k = 64 (8 k-steps)
#pragma unroll
        for (int kc = 0; kc < 8; kc++) {
            unsigned bfr[4][2];
#pragma unroll
            for (int j = 0; j < 4; j++) {
                int f = h * 32 + j * 8 + g;
                int k0 = kc * 8 + tg, k1 = k0 + 4;
                bfr[j][0] = __float_as_uint(sH[k0 * 128 + (f ^ ((k0 & 3) << 3))]);
                bfr[j][1] = __float_as_uint(sH[k1 * 128 + (f ^ ((k1 & 3) << 3))]);
            }
#pragma unroll
            for (int sp = 0; sp < 2; sp++) {
                int row = s0r + sp * 32 + g;
                const float* pr = sP + (h * 64 + row) * 66 + kc * 8;
                unsigned a[4];
                a[0] = __float_as_uint(pr[tg]);
                a[2] = __float_as_uint(pr[tg + 4]);
                a[1] = __float_as_uint(pr[8 * 66 + tg]);
                a[3] = __float_as_uint(pr[8 * 66 + tg + 4]);
#pragma unroll
                for (int j = 0; j < 4; j++) mma_tf32(c[sp][j], a, bfr[j]);
            }
        }
    }
    sS[ph * 64 + pn] = Sreg;
    __syncthreads();

    // epilogue: /S, ELU, store g_m0
#pragma unroll
    for (int sp = 0; sp < 2; sp++) {
        int rbase = s0r + sp * 32 + g;
        float inv0 = 1.0f / sS[h * 64 + rbase];
        float inv8 = 1.0f / sS[h * 64 + rbase + 8];
#pragma unroll
        for (int j = 0; j < 4; j++) {
            int f = h * 32 + j * 8 + 2 * tg;
            float v0 = c[sp][j][0] * inv0, v1 = c[sp][j][1] * inv0;
            float v2 = c[sp][j][2] * inv8, v3 = c[sp][j][3] * inv8;
            v0 = v0 > 0.0f ? v0 : expm1f(v0);
            v1 = v1 > 0.0f ? v1 : expm1f(v1);
            v2 = v2 > 0.0f ? v2 : expm1f(v2);
            v3 = v3 > 0.0f ? v3 : expm1f(v3);
            size_t o0 = ((size_t)b * NN + nb + rbase) * FIN + f;
            *(float2*)&g_m0[o0] = make_float2(v0, v1);
            *(float2*)&g_m0[o0 + 8 * FIN] = make_float2(v2, v3);
        }
    }
}

// ------------------------- attn1: tf32 mma, 1 head, D=128 -------------------------
// CTA: 64 rows, 8 warps. warp w: stripe st=w&3, col-half ch=w>>2 (64 cols, 8 N-frags).
// smem floats: sP[64][66] | sH[64][128] | sd[512] | ss[64] | sS[64] | mk[64][16]
#define A1_SMEM ((64*66 + 64*128 + 512 + 64 + 64 + 64*16) * 4)

__global__ __launch_bounds__(256, 2) void k_attn1_mma() {
    extern __shared__ float sm[];
    float* sP = sm;
    float* sH = sP + 64 * 66;
    float* sd = sH + 64 * 128;
    float* ss = sd + 512;
    float* sS = ss + 64;
    unsigned* mk = (unsigned*)(sS + 64);

    int b = blockIdx.y, nb = blockIdx.x * 64;
    int t = threadIdx.x;
    int w = t >> 5, lane = t & 31;
    int g = lane >> 2, tg = lane & 3;

    for (int i = t; i < 512; i += 256) sd[i] = g_d1[b * NN + i];
    if (t < 64) ss[t] = g_s1[b * NN + nb + t];
    for (int i = t; i < 64 * NW; i += 256) mk[i] = g_mask[(b * NN + nb) * NW + i];
    __syncthreads();

    int pn = t >> 2, pq = t & 3;        // P-compute: row pn, 16-m slice pq
    float sval = ss[pn];
    float Sreg = 0.0f;

    int st = w & 3, ch = w >> 2;
    float c[8][4];
#pragma unroll
    for (int j = 0; j < 8; j++)
#pragma unroll
        for (int e = 0; e < 4; e++) c[j][e] = 0.0f;

    for (int mt = 0; mt < 8; mt++) {
        __syncthreads();
        for (int i = t; i < 64 * 32; i += 256) {
            int r = i >> 5, c4 = (i & 31) * 4;
            float4 v = *(const float4*)&g_h1[((size_t)b * NN + mt * 64 + r) * FOUT + c4];
            int cs = c4 ^ ((r & 3) << 3);
            float4 o;
            o.x = __uint_as_float(f2tf(v.x)); o.y = __uint_as_float(f2tf(v.y));
            o.z = __uint_as_float(f2tf(v.z)); o.w = __uint_as_float(f2tf(v.w));
            *(float4*)&sH[r * 128 + cs] = o;
        }
        {
            unsigned bits = mk[pn * NW + mt * 2 + (pq >> 1)];
            int sh0 = (pq & 1) * 16;
            const float* dp = sd + mt * 64 + pq * 16;
            float* pp = sP + pn * 66 + pq * 16;
#pragma unroll
            for (int j = 0; j < 16; j++) {
                float z = lrelu(sval + dp[j]);
                float wg = ((bits >> (sh0 + j)) & 1u) ? __expf(z) : 0.0f;
                Sreg += wg;
                pp[j] = __uint_as_float(f2tf(wg));
            }
        }
        __syncthreads();
#pragma unroll
        for (int kc = 0; kc < 8; kc++) {
            int row = st * 16 + g;
            const float* pr = sP + row * 66 + kc * 8;
            unsigned a[4];
            a[0] = __float_as_uint(pr[tg]);
            a[2] = __float_as_uint(pr[tg + 4]);
            a[1] = __float_as_uint(pr[8 * 66 + tg]);
            a[3] = __float_as_uint(pr[8 * 66 + tg + 4]);
            int k0 = kc * 8 + tg, k1 = k0 + 4;
            int sw0 = (k0 & 3) << 3, sw1 = (k1 & 3) << 3;
#pragma unroll
            for (int j = 0; j < 8; j++) {
                int f = ch * 64 + j * 8 + g;
                unsigned bfr[2];
                bfr[0] = __float_as_uint(sH[k0 * 128 + (f ^ sw0)]);
                bfr[1] = __float_as_uint(sH[k1 * 128 + (f ^ sw1)]);
                mma_tf32(c[j], a, bfr);
            }
        }
    }
    // reduce S over the 4 pq-slices of each row (lanes t, t^1, t^2 share pn)
    Sreg = qsum(Sreg);
    if (pq == 0) sS[pn] = Sreg;
    __syncthreads();

    int rbase = st * 16 + g;
    float inv0 = 1.0f / sS[rbase];
    float inv8 = 1.0f / sS[rbase + 8];
#pragma unroll
    for (int j = 0; j < 8; j++) {
        int f = ch * 64 + j * 8 + 2 * tg;
        size_t o0 = ((size_t)b * NN + nb + rbase) * FOUT + f;
        *(float2*)&g_m1[o0] = make_float2(c[j][0] * inv0, c[j][1] * inv0);
        *(float2*)&g_m1[o0 + 8 * FOUT] = make_float2(c[j][2] * inv8, c[j][3] * inv8);
    }
}

// ------------------------- kernel: fused tail -------------------------
#define TS_STRIDE 260
#define MS_STRIDE 132
#define TAIL_SMEM ((64 * TS_STRIDE + 2 * 64 * MS_STRIDE + 32 * 128) * 4)

__global__ void k_tail(const float* __restrict__ x,
                       const float* __restrict__ ln1g, const float* __restrict__ ln1b,
                       const float* __restrict__ linW, const float* __restrict__ linb,
                       const float* __restrict__ meW0, const float* __restrict__ meb0,
                       const float* __restrict__ meW1, const float* __restrict__ meb1,
                       const float* __restrict__ ln2g, const float* __restrict__ ln2b,
                       const float* __restrict__ ohW, const float* __restrict__ ohb,
                       const float* __restrict__ ln3g, const float* __restrict__ ln3b,
                       float* __restrict__ out) {
    extern __shared__ float sm[];
    float* ts = sm;
    float* ms = ts + 64 * TS_STRIDE;
    float* us = ms + 64 * MS_STRIDE;
    float* ws = us + 64 * MS_STRIDE;

    int b = blockIdx.y, nb = blockIdx.x * 64;
    int t = threadIdx.x, c = t & 3, nl = t >> 2;
    int n = nb + nl;

    for (int i = t; i < 64 * 256; i += 256) {
        int r = i >> 8, j = i & 255;
        size_t row = (size_t)b * NN + nb + r;
        float v = (j < 128) ? x[row * FIN + j] : g_m1[row * FOUT + (j - 128)];
        ts[r * TS_STRIDE + j] = v;
    }
    __syncthreads();

    float sum = 0, sq = 0;
#pragma unroll 8
    for (int i = 0; i < 64; i++) {
        float v = ts[nl * TS_STRIDE + c * 64 + i];
        sum += v; sq += v * v;
    }
    sum = qsum(sum); sq = qsum(sq);
    float mu = sum * (1.0f / 256.0f);
    float rstd = rsqrtf(sq * (1.0f / 256.0f) - mu * mu + 1e-5f);
#pragma unroll 8
    for (int i = 0; i < 64; i++) {
        int j = c * 64 + i;
        float v = ts[nl * TS_STRIDE + j];
        ts[nl * TS_STRIDE + j] = (v - mu) * rstd * ln1g[j] + ln1b[j];
    }

    float mreg[32];
#pragma unroll
    for (int d = 0; d < 32; d++) mreg[d] = 0.0f;
    mm_acc(linW, ts, TS_STRIDE, ws, mreg, 8, c, nl, t);
#pragma unroll
    for (int d = 0; d < 32; d++) {
        mreg[d] += linb[c * 32 + d];
        ms[nl * MS_STRIDE + c * 32 + d] = mreg[d];
    }

    float a2[32];
#pragma unroll
    for (int d = 0; d < 32; d++) a2[d] = 0.0f;
    mm_acc(meW0, ms, MS_STRIDE, ws, a2, 4, c, nl, t);
#pragma unroll
    for (int d = 0; d < 32; d++)
        us[nl * MS_STRIDE + c * 32 + d] = gelu_exact(a2[d] + meb0[c * 32 + d]);

    float a3[32];
#pragma unroll
    for (int d = 0; d < 32; d++) a3[d] = 0.0f;
    mm_acc(meW1, us, MS_STRIDE, ws, a3, 4, c, nl, t);
    sum = 0; sq = 0;
#pragma unroll
    for (int d = 0; d < 32; d++) {
        a3[d] = a3[d] + meb1[c * 32 + d] + mreg[d];
        sum += a3[d]; sq += a3[d] * a3[d];
    }
    sum = qsum(sum); sq = qsum(sq);
    mu = sum * (1.0f / 128.0f);
    rstd = rsqrtf(sq * (1.0f / 128.0f) - mu * mu + 1e-5f);
    __syncthreads();
#pragma unroll
    for (int d = 0; d < 32; d++) {
        int o = c * 32 + d;
        us[nl * MS_STRIDE + o] = (a3[d] - mu) * rstd * ln2g[o] + ln2b[o];
    }

    float a4[32];
#pragma unroll
    for (int d = 0; d < 32; d++) a4[d] = 0.0f;
    mm_acc(ohW, us, MS_STRIDE, ws, a4, 4, c, nl, t);
    sum = 0; sq = 0;
#pragma unroll
    for (int d = 0; d < 32; d++) {
        float v = gelu_exact(a4[d] + ohb[c * 32 + d]);
        a4[d] = v;
        sum += v; sq += v * v;
    }
    sum = qsum(sum); sq = qsum(sq);
    mu = sum * (1.0f / 128.0f);
    rstd = rsqrtf(sq * (1.0f / 128.0f) - mu * mu + 1e-5f);

    float* op = out + ((size_t)b * NN + n) * FOUT + c * 32;
#pragma unroll
    for (int d4 = 0; d4 < 8; d4++) {
        float r0 = (a4[4 * d4 + 0] - mu) * rstd * ln3g[c * 32 + 4 * d4 + 0] + ln3b[c * 32 + 4 * d4 + 0];
        float r1 = (a4[4 * d4 + 1] - mu) * rstd * ln3g[c * 32 + 4 * d4 + 1] + ln3b[c * 32 + 4 * d4 + 1];
        float r2 = (a4[4 * d4 + 2] - mu) * rstd * ln3g[c * 32 + 4 * d4 + 2] + ln3b[c * 32 + 4 * d4 + 2];
        float r3 = (a4[4 * d4 + 3] - mu) * rstd * ln3g[c * 32 + 4 * d4 + 3] + ln3b[c * 32 + 4 * d4 + 3];
        ((float4*)op)[d4] = make_float4(r0, r1, r2, r3);
    }
}

// ------------------------- launch -------------------------
extern "C" void kernel_launch(void* const* d_in, const int* in_sizes, int n_in,
                              void* d_out, int out_size) {
    const float* x    = (const float*)d_in[0];
    const int*   grp  = (const int*)  d_in[1];
    const float* W0   = (const float*)d_in[2];
    const float* as0  = (const float*)d_in[3];
    const float* ad0  = (const float*)d_in[4];
    const float* W1   = (const float*)d_in[5];
    const float* as1  = (const float*)d_in[6];
    const float* ad1  = (const float*)d_in[7];
    const float* ln1g = (const float*)d_in[8];
    const float* ln1b = (const float*)d_in[9];
    const float* linW = (const float*)d_in[10];
    const float* linb = (const float*)d_in[11];
    const float* meW0 = (const float*)d_in[12];
    const float* meb0 = (const float*)d_in[13];
    const float* meW1 = (const float*)d_in[14];
    const float* meb1 = (const float*)d_in[15];
    const float* ln2g = (const float*)d_in[16];
    const float* ln2b = (const float*)d_in[17];
    const float* ohW  = (const float*)d_in[18];
    const float* ohb  = (const float*)d_in[19];
    const float* ln3g = (const float*)d_in[20];
    const float* ln3b = (const float*)d_in[21];
    float* out = (float*)d_out;

    cudaFuncSetAttribute(k_tail, cudaFuncAttributeMaxDynamicSharedMemorySize, TAIL_SMEM);
    cudaFuncSetAttribute(k_attn0_mma, cudaFuncAttributeMaxDynamicSharedMemorySize, A0_SMEM);
    cudaFuncSetAttribute(k_attn1_mma, cudaFuncAttributeMaxDynamicSharedMemorySize, A1_SMEM);

    k_mask<<<(BB * NN * NN) / 256, 256>>>(grp);
    k_proj0<<<dim3(NN / 128, BB), 256>>>(x, W0, as0, ad0);
    k_attn0_mma<<<dim3(NN / 64, BB), 256, A0_SMEM>>>();
    k_proj1<<<dim3(NN / 128, BB), 256>>>(W1, as1, ad1);
    k_attn1_mma<<<dim3(NN / 64, BB), 256, A1_SMEM>>>();
    k_tail<<<dim3(NN / 64, BB), 256, TAIL_SMEM>>>(x, ln1g, ln1b, linW, linb,
                                                  meW0, meb0, meW1, meb1,
                                                  ln2g, ln2b, ohW, ohb,
                                                  ln3g, ln3b, out);
}

// round 4
// speedup vs baseline: 4.4083x; 1.8128x over previous
#include <cuda_runtime.h>
#include <math.h>

#define BB 32
#define NN 512
#define FIN 128
#define HID 32
#define NH 4
#define FOUT 128
#define NW (NN/32)   // 16 mask words per row

// ------------------------- scratch (device globals; no allocation) -------------------------
__device__ float    g_h0[(size_t)BB*NN*FIN];
__device__ float    g_s0[BB*NH*NN];
__device__ float    g_d0[BB*NH*NN];
__device__ float    g_m0[(size_t)BB*NN*FIN];   // elu(gat0 out)
__device__ float    g_h1[(size_t)BB*NN*FOUT];
__device__ float    g_s1[BB*NN];
__device__ float    g_d1[BB*NN];
__device__ float    g_m1[(size_t)BB*NN*FOUT];  // gat1 out
__device__ unsigned g_mask[BB*NN*NW];

// ------------------------- helpers -------------------------
__device__ __forceinline__ float qsum(float v) {
    v += __shfl_xor_sync(0xffffffffu, v, 1);
    v += __shfl_xor_sync(0xffffffffu, v, 2);
    return v;
}
__device__ __forceinline__ float lrelu(float z) { return z > 0.0f ? z : 0.2f * z; }
__device__ __forceinline__ float gelu_exact(float v) {
    return 0.5f * v * (1.0f + erff(v * 0.70710678118654752f));
}
__device__ __forceinline__ unsigned f2tf(float f) {
    unsigned u; asm("cvt.rna.tf32.f32 %0, %1;" : "=r"(u) : "f"(f)); return u;
}
__device__ __forceinline__ float tfh(float f) { return __uint_as_float(f2tf(f)); }
__device__ __forceinline__ void mma_tf32(float c[4], const unsigned a[4], const unsigned b[2]) {
    asm volatile("mma.sync.aligned.m16n8k8.row.col.f32.tf32.tf32.f32 "
                 "{%0,%1,%2,%3}, {%4,%5,%6,%7}, {%8,%9}, {%0,%1,%2,%3};"
                 : "+f"(c[0]), "+f"(c[1]), "+f"(c[2]), "+f"(c[3])
                 : "r"(a[0]), "r"(a[1]), "r"(a[2]), "r"(a[3]), "r"(b[0]), "r"(b[1]));
}

// stage W[ktbase + r][0..127] for r in 0..63 -> ws[64][128], tf32 + XOR swizzle
__device__ __forceinline__ void stage_w_tf(const float* __restrict__ W, float* ws,
                                           int ktbase, int t) {
    for (int i = t; i < 64 * 32; i += 256) {
        int r = i >> 5, c4 = (i & 31) * 4;
        float4 v = *(const float4*)&W[(size_t)(ktbase + r) * 128 + c4];
        int cs = c4 ^ ((r & 3) << 3);
        float4 o;
        o.x = tfh(v.x); o.y = tfh(v.y); o.z = tfh(v.z); o.w = tfh(v.w);
        *(float4*)&ws[r * 128 + cs] = o;
    }
}

// ------------------------- kernel: adjacency -> bitmask -------------------------
__global__ void k_mask(const int* __restrict__ graph) {
    int idx = blockIdx.x * 256 + threadIdx.x;
    int m = idx & (NN - 1);
    int n = (idx >> 9) & (NN - 1);
    bool pred = (graph[idx] > 0) || (m == n);
    unsigned w = __ballot_sync(0xffffffffu, pred);
    if ((m & 31) == 0) g_mask[idx >> 5] = w;
}

// ------------------------- proj (mma): h = X@W [128x128x128 per CTA], + s/d logits -----------
// 8 warps: st=w&3 (32-row stripe), ch=w>>2 (64-col half). Accum c[2][8][4].
// MH=true: proj0 (4 heads, per-head s/d, head boundary aligns with ch). MH=false: proj1.
#define PROJ_SMEM ((128*68 + 64*128 + 256) * 4)

template<bool MH>
__global__ __launch_bounds__(256, 2) void k_proj_mma(const float* __restrict__ Xin,
                                                     const float* __restrict__ Wg,
                                                     const float* __restrict__ av,
                                                     const float* __restrict__ bv) {
    extern __shared__ float sm[];
    float* xs = sm;              // 128 x 68 (padded), tf32 bits
    float* ws = xs + 128 * 68;   // 64 x 128 XOR-swizzled, tf32 bits
    float* sdb = ws + 64 * 128;  // 256: s/d accum for MH=false

    int b = blockIdx.y, nb = blockIdx.x * 128;
    int t = threadIdx.x, w = t >> 5, lane = t & 31, g = lane >> 2, tg = lane & 3;
    int st = w & 3, ch = w >> 2;

    if (!MH) sdb[t] = 0.0f;

    const float* src = MH ? (Xin + ((size_t)b * NN + nb) * 128)
                          : ((const float*)g_m0 + ((size_t)b * NN + nb) * 128);

    float c[2][8][4];
#pragma unroll
    for (int mf = 0; mf < 2; mf++)
#pragma unroll
        for (int j = 0; j < 8; j++)
#pragma unroll
            for (int e = 0; e < 4; e++) c[mf][j][e] = 0.0f;

    for (int kt = 0; kt < 2; kt++) {
        __syncthreads();
        // stage A chunk: 128 rows x 64 k (tf32, stride 68)
        for (int i = t; i < 128 * 16; i += 256) {
            int r = i >> 4, c4 = (i & 15) * 4;
            float4 v = *(const float4*)&src[r * 128 + kt * 64 + c4];
            float* dst = xs + r * 68 + c4;
            dst[0] = tfh(v.x); dst[1] = tfh(v.y); dst[2] = tfh(v.z); dst[3] = tfh(v.w);
        }
        stage_w_tf(Wg, ws, kt * 64, t);
        __syncthreads();
        for (int kc = 0; kc < 8; kc++) {
            unsigned a[2][4];
#pragma unroll
            for (int mf = 0; mf < 2; mf++) {
                const float* pr = xs + (st * 32 + mf * 16 + g) * 68 + kc * 8;
                a[mf][0] = __float_as_uint(pr[tg]);
                a[mf][1] = __float_as_uint(pr[8 * 68 + tg]);
                a[mf][2] = __float_as_uint(pr[tg + 4]);
                a[mf][3] = __float_as_uint(pr[8 * 68 + tg + 4]);
            }
            int k0 = kc * 8 + tg, k1 = k0 + 4;
            int sw0 = (k0 & 3) << 3, sw1 = (k1 & 3) << 3;
#pragma unroll
            for (int j = 0; j < 8; j++) {
                int f = ch * 64 + j * 8 + g;
                unsigned bfr[2];
                bfr[0] = __float_as_uint(ws[k0 * 128 + (f ^ sw0)]);
                bfr[1] = __float_as_uint(ws[k1 * 128 + (f ^ sw1)]);
                mma_tf32(c[0][j], a[0], bfr);
                mma_tf32(c[1][j], a[1], bfr);
            }
        }
    }

    // write h
    float* H = MH ? (float*)g_h0 : (float*)g_h1;
#pragma unroll
    for (int mf = 0; mf < 2; mf++) {
        int row = st * 32 + mf * 16 + g;
        size_t base = ((size_t)b * NN + nb + row) * 128;
#pragma unroll
        for (int j = 0; j < 8; j++) {
            int col = ch * 64 + j * 8 + 2 * tg;
            *(float2*)&H[base + col] = make_float2(c[mf][j][0], c[mf][j][1]);
            *(float2*)&H[base + 8 * 128 + col] = make_float2(c[mf][j][2], c[mf][j][3]);
        }
    }

    if (MH) {
        // per-head s/d: warp ch owns heads 2ch (j 0-3) and 2ch+1 (j 4-7)
        float sv[2][2][2], dv[2][2][2];
#pragma unroll
        for (int mf = 0; mf < 2; mf++)
#pragma unroll
            for (int hh = 0; hh < 2; hh++)
#pragma unroll
                for (int rr = 0; rr < 2; rr++) { sv[mf][hh][rr] = 0.0f; dv[mf][hh][rr] = 0.0f; }
#pragma unroll
        for (int mf = 0; mf < 2; mf++)
#pragma unroll
            for (int j = 0; j < 8; j++)
#pragma unroll
                for (int e = 0; e < 4; e++) {
                    int col = ch * 64 + j * 8 + 2 * tg + (e & 1);
                    sv[mf][j >> 2][e >> 1] += c[mf][j][e] * av[col];
                    dv[mf][j >> 2][e >> 1] += c[mf][j][e] * bv[col];
                }
#pragma unroll
        for (int mf = 0; mf < 2; mf++)
#pragma unroll
            for (int hh = 0; hh < 2; hh++)
#pragma unroll
                for (int rr = 0; rr < 2; rr++) {
                    sv[mf][hh][rr] = qsum(sv[mf][hh][rr]);
                    dv[mf][hh][rr] = qsum(dv[mf][hh][rr]);
                }
        if (tg == 0) {
#pragma unroll
            for (int mf = 0; mf < 2; mf++)
#pragma unroll
                for (int hh = 0; hh < 2; hh++)
#pragma unroll
                    for (int rr = 0; rr < 2; rr++) {
                        int r = st * 32 + mf * 16 + g + rr * 8;
                        int hidx = b * NH + 2 * ch + hh;
                        g_s0[hidx * NN + nb + r] = sv[mf][hh][rr];
                        g_d0[hidx * NN + nb + r] = dv[mf][hh][rr];
                    }
        }
    } else {
        float sv[2][2], dv[2][2];
#pragma unroll
        for (int mf = 0; mf < 2; mf++)
#pragma unroll
            for (int rr = 0; rr < 2; rr++) { sv[mf][rr] = 0.0f; dv[mf][rr] = 0.0f; }
#pragma unroll
        for (int mf = 0; mf < 2; mf++)
#pragma unroll
            for (int j = 0; j < 8; j++)
#pragma unroll
                for (int e = 0; e < 4; e++) {
                    int col = ch * 64 + j * 8 + 2 * tg + (e & 1);
                    sv[mf][e >> 1] += c[mf][j][e] * av[col];
                    dv[mf][e >> 1] += c[mf][j][e] * bv[col];
                }
#pragma unroll
        for (int mf = 0; mf < 2; mf++)
#pragma unroll
            for (int rr = 0; rr < 2; rr++) {
                sv[mf][rr] = qsum(sv[mf][rr]);
                dv[mf][rr] = qsum(dv[mf][rr]);
            }
        if (tg == 0) {
#pragma unroll
            for (int mf = 0; mf < 2; mf++)
#pragma unroll
                for (int rr = 0; rr < 2; rr++) {
                    int r = st * 32 + mf * 16 + g + rr * 8;
                    atomicAdd(&sdb[2 * r], sv[mf][rr]);
                    atomicAdd(&sdb[2 * r + 1], dv[mf][rr]);
                }
        }
        __syncthreads();
        if (t < 128) {
            g_s1[b * NN + nb + t] = sdb[2 * t];
            g_d1[b * NN + nb + t] = sdb[2 * t + 1];
        }
    }
}

// ------------------------- attn0: tf32 mma flash-style, 4 heads, D=32 -------------------------
#define A0_SMEM ((4*64*66 + 64*128 + 4*512 + 4*64 + 4*64 + 64*16) * 4)

__global__ __launch_bounds__(256, 2) void k_attn0_mma() {
    extern __shared__ float sm[];
    float* sP = sm;
    float* sH = sP + 4 * 64 * 66;
    float* sd = sH + 64 * 128;
    float* ss = sd + 4 * 512;
    float* sS = ss + 4 * 64;
    unsigned* mk = (unsigned*)(sS + 4 * 64);

    int b = blockIdx.y, nb = blockIdx.x * 64;
    int t = threadIdx.x;
    int w = t >> 5, lane = t & 31;
    int g = lane >> 2, tg = lane & 3;

    for (int i = t; i < 4 * 512; i += 256) sd[i] = g_d0[b * NH * NN + i];
    for (int i = t; i < 4 * 64; i += 256) {
        int hh = i >> 6, n = i & 63;
        ss[i] = g_s0[(b * NH + hh) * NN + nb + n];
    }
    for (int i = t; i < 64 * NW; i += 256) mk[i] = g_mask[(b * NN + nb) * NW + i];
    __syncthreads();

    int ph = t >> 6, pn = t & 63;
    float sval = ss[ph * 64 + pn];
    float Sreg = 0.0f;

    int h = w >> 1;
    int s0r = (w & 1) * 16;
    float c[2][4][4];
#pragma unroll
    for (int sp = 0; sp < 2; sp++)
#pragma unroll
        for (int j = 0; j < 4; j++)
#pragma unroll
            for (int e = 0; e < 4; e++) c[sp][j][e] = 0.0f;

    for (int mt = 0; mt < 8; mt++) {
        __syncthreads();
        for (int i = t; i < 64 * 32; i += 256) {
            int r = i >> 5, c4 = (i & 31) * 4;
            float4 v = *(const float4*)&g_h0[((size_t)b * NN + mt * 64 + r) * FIN + c4];
            int cs = c4 ^ ((r & 3) << 3);
            float4 o;
            o.x = tfh(v.x); o.y = tfh(v.y); o.z = tfh(v.z); o.w = tfh(v.w);
            *(float4*)&sH[r * 128 + cs] = o;
        }
        {
            unsigned bits0 = mk[pn * NW + mt * 2];
            unsigned bits1 = mk[pn * NW + mt * 2 + 1];
            const float* dp = sd + ph * 512 + mt * 64;
            float* pp = sP + (ph * 64 + pn) * 66;
#pragma unroll 8
            for (int m = 0; m < 32; m++) {
                float z = lrelu(sval + dp[m]);
                float wg = ((bits0 >> m) & 1u) ? __expf(z) : 0.0f;
                Sreg += wg;
                pp[m] = __uint_as_float(f2tf(wg));
            }
#pragma unroll 8
            for (int m = 0; m < 32; m++) {
                float z = lrelu(sval + dp[32 + m]);
                float wg = ((bits1 >> m) & 1u) ? __expf(z) : 0.0f;
                Sreg += wg;
                pp[32 + m] = __uint_as_float(f2tf(wg));
            }
        }
        __syncthreads();
#pragma unroll
        for (int kc = 0; kc < 8; kc++) {
            unsigned bfr[4][2];
#pragma unroll
            for (int j = 0; j < 4; j++) {
                int f = h * 32 + j * 8 + g;
                int k0 = kc * 8 + tg, k1 = k0 + 4;
                bfr[j][0] = __float_as_uint(sH[k0 * 128 + (f ^ ((k0 & 3) << 3))]);
                bfr[j][1] = __float_as_uint(sH[k1 * 128 + (f ^ ((k1 & 3) << 3))]);
            }
#pragma unroll
            for (int sp = 0; sp < 2; sp++) {
                int row = s0r + sp * 32 + g;
                const float* pr = sP + (h * 64 + row) * 66 + kc * 8;
                unsigned a[4];
                a[0] = __float_as_uint(pr[tg]);
                a[2] = __float_as_uint(pr[tg + 4]);
                a[1] = __float_as_uint(pr[8 * 66 + tg]);
                a[3] = __float_as_uint(pr[8 * 66 + tg + 4]);
#pragma unroll
                for (int j = 0; j < 4; j++) mma_tf32(c[sp][j], a, bfr[j]);
            }
        }
    }
    sS[ph * 64 + pn] = Sreg;
    __syncthreads();

#pragma unroll
    for (int sp = 0; sp < 2; sp++) {
        int rbase = s0r + sp * 32 + g;
        float inv0 = 1.0f / sS[h * 64 + rbase];
        float inv8 = 1.0f / sS[h * 64 + rbase + 8];
#pragma unroll
        for (int j = 0; j < 4; j++) {
            int f = h * 32 + j * 8 + 2 * tg;
            float v0 = c[sp][j][0] * inv0, v1 = c[sp][j][1] * inv0;
            float v2 = c[sp][j][2] * inv8, v3 = c[sp][j][3] * inv8;
            v0 = v0 > 0.0f ? v0 : expm1f(v0);
            v1 = v1 > 0.0f ? v1 : expm1f(v1);
            v2 = v2 > 0.0f ? v2 : expm1f(v2);
            v3 = v3 > 0.0f ? v3 : expm1f(v3);
            size_t o0 = ((size_t)b * NN + nb + rbase) * FIN + f;
            *(float2*)&g_m0[o0] = make_float2(v0, v1);
            *(float2*)&g_m0[o0 + 8 * FIN] = make_float2(v2, v3);
        }
    }
}

// ------------------------- attn1: tf32 mma, 1 head, D=128 -------------------------
#define A1_SMEM ((64*66 + 64*128 + 512 + 64 + 64 + 64*16) * 4)

__global__ __launch_bounds__(256, 2) void k_attn1_mma() {
    extern __shared__ float sm[];
    float* sP = sm;
    float* sH = sP + 64 * 66;
    float* sd = sH + 64 * 128;
    float* ss = sd + 512;
    float* sS = ss + 64;
    unsigned* mk = (unsigned*)(sS + 64);

    int b = blockIdx.y, nb = blockIdx.x * 64;
    int t = threadIdx.x;
    int w = t >> 5, lane = t & 31;
    int g = lane >> 2, tg = lane & 3;

    for (int i = t; i < 512; i += 256) sd[i] = g_d1[b * NN + i];
    if (t < 64) ss[t] = g_s1[b * NN + nb + t];
    for (int i = t; i < 64 * NW; i += 256) mk[i] = g_mask[(b * NN + nb) * NW + i];
    __syncthreads();

    int pn = t >> 2, pq = t & 3;
    float sval = ss[pn];
    float Sreg = 0.0f;

    int st = w & 3, ch = w >> 2;
    float c[8][4];
#pragma unroll
    for (int j = 0; j < 8; j++)
#pragma unroll
        for (int e = 0; e < 4; e++) c[j][e] = 0.0f;

    for (int mt = 0; mt < 8; mt++) {
        __syncthreads();
        for (int i = t; i < 64 * 32; i += 256) {
            int r = i >> 5, c4 = (i & 31) * 4;
            float4 v = *(const float4*)&g_h1[((size_t)b * NN + mt * 64 + r) * FOUT + c4];
            int cs = c4 ^ ((r & 3) << 3);
            float4 o;
            o.x = tfh(v.x); o.y = tfh(v.y); o.z = tfh(v.z); o.w = tfh(v.w);
            *(float4*)&sH[r * 128 + cs] = o;
        }
        {
            unsigned bits = mk[pn * NW + mt * 2 + (pq >> 1)];
            int sh0 = (pq & 1) * 16;
            const float* dp = sd + mt * 64 + pq * 16;
            float* pp = sP + pn * 66 + pq * 16;
#pragma unroll
            for (int j = 0; j < 16; j++) {
                float z = lrelu(sval + dp[j]);
                float wg = ((bits >> (sh0 + j)) & 1u) ? __expf(z) : 0.0f;
                Sreg += wg;
                pp[j] = __uint_as_float(f2tf(wg));
            }
        }
        __syncthreads();
#pragma unroll
        for (int kc = 0; kc < 8; kc++) {
            int row = st * 16 + g;
            const float* pr = sP + row * 66 + kc * 8;
            unsigned a[4];
            a[0] = __float_as_uint(pr[tg]);
            a[2] = __float_as_uint(pr[tg + 4]);
            a[1] = __float_as_uint(pr[8 * 66 + tg]);
            a[3] = __float_as_uint(pr[8 * 66 + tg + 4]);
            int k0 = kc * 8 + tg, k1 = k0 + 4;
            int sw0 = (k0 & 3) << 3, sw1 = (k1 & 3) << 3;
#pragma unroll
            for (int j = 0; j < 8; j++) {
                int f = ch * 64 + j * 8 + g;
                unsigned bfr[2];
                bfr[0] = __float_as_uint(sH[k0 * 128 + (f ^ sw0)]);
                bfr[1] = __float_as_uint(sH[k1 * 128 + (f ^ sw1)]);
                mma_tf32(c[j], a, bfr);
            }
        }
    }
    Sreg = qsum(Sreg);
    if (pq == 0) sS[pn] = Sreg;
    __syncthreads();

    int rbase = st * 16 + g;
    float inv0 = 1.0f / sS[rbase];
    float inv8 = 1.0f / sS[rbase + 8];
#pragma unroll
    for (int j = 0; j < 8; j++) {
        int f = ch * 64 + j * 8 + 2 * tg;
        size_t o0 = ((size_t)b * NN + nb + rbase) * FOUT + f;
        *(float2*)&g_m1[o0] = make_float2(c[j][0] * inv0, c[j][1] * inv0);
        *(float2*)&g_m1[o0 + 8 * FOUT] = make_float2(c[j][2] * inv8, c[j][3] * inv8);
    }
}

// ------------------------- fused tail (mma matmuls) -------------------------
// 8 warps: st=w&1 (32-row stripe of the 64 rows), ch=w>>1 (32-col quarter).
#define TS_STRIDE 260
#define MS_STRIDE 132
#define TAIL_SMEM ((64*TS_STRIDE + 2*64*MS_STRIDE + 64*128) * 4)

__device__ __forceinline__ void tail_mm(const float* __restrict__ Wg, const float* A, int astride,
                                        int K, float* ws, float c[2][4][4],
                                        int st, int ch, int g, int tg, int t) {
    for (int kt = 0; kt < K; kt += 64) {
        __syncthreads();
        stage_w_tf(Wg, ws, kt, t);
        __syncthreads();
        for (int kc = 0; kc < 8; kc++) {
            unsigned a[2][4];
#pragma unroll
            for (int mf = 0; mf < 2; mf++) {
                const float* pr = A + (st * 32 + mf * 16 + g) * astride + kt + kc * 8;
                a[mf][0] = f2tf(pr[tg]);
                a[mf][1] = f2tf(pr[8 * astride + tg]);
                a[mf][2] = f2tf(pr[tg + 4]);
                a[mf][3] = f2tf(pr[8 * astride + tg + 4]);
            }
            int k0 = kc * 8 + tg, k1 = k0 + 4;
            int sw0 = (k0 & 3) << 3, sw1 = (k1 & 3) << 3;
#pragma unroll
            for (int j = 0; j < 4; j++) {
                int f = ch * 32 + j * 8 + g;
                unsigned bfr[2];
                bfr[0] = __float_as_uint(ws[k0 * 128 + (f ^ sw0)]);
                bfr[1] = __float_as_uint(ws[k1 * 128 + (f ^ sw1)]);
                mma_tf32(c[0][j], a[0], bfr);
                mma_tf32(c[1][j], a[1], bfr);
            }
        }
    }
}

__device__ __forceinline__ void frag_store(float* D, int dstride, float c[2][4][4],
                                           int st, int ch, int g, int tg) {
#pragma unroll
    for (int mf = 0; mf < 2; mf++) {
        int row = st * 32 + mf * 16 + g;
#pragma unroll
        for (int j = 0; j < 4; j++) {
            int col = ch * 32 + j * 8 + 2 * tg;
            *(float2*)&D[row * dstride + col] = make_float2(c[mf][j][0], c[mf][j][1]);
            *(float2*)&D[(row + 8) * dstride + col] = make_float2(c[mf][j][2], c[mf][j][3]);
        }
    }
}

__device__ __forceinline__ void frag_zero(float c[2][4][4]) {
#pragma unroll
    for (int mf = 0; mf < 2; mf++)
#pragma unroll
        for (int j = 0; j < 4; j++)
#pragma unroll
            for (int e = 0; e < 4; e++) c[mf][j][e] = 0.0f;
}

__global__ __launch_bounds__(256, 1) void k_tail(const float* __restrict__ x,
                       const float* __restrict__ ln1g, const float* __restrict__ ln1b,
                       const float* __restrict__ linW, const float* __restrict__ linb,
                       const float* __restrict__ meW0, const float* __restrict__ meb0,
                       const float* __restrict__ meW1, const float* __restrict__ meb1,
                       const float* __restrict__ ln2g, const float* __restrict__ ln2b,
                       const float* __restrict__ ohW, const float* __restrict__ ohb,
                       const float* __restrict__ ln3g, const float* __restrict__ ln3b,
                       float* __restrict__ out) {
    extern __shared__ float sm[];
    float* ts = sm;                      // 64 x 260
    float* ms = ts + 64 * TS_STRIDE;     // 64 x 132
    float* us = ms + 64 * MS_STRIDE;     // 64 x 132
    float* ws = us + 64 * MS_STRIDE;     // 64 x 128 weight chunk

    int b = blockIdx.y, nb = blockIdx.x * 64;
    int t = threadIdx.x, cq = t & 3, nl = t >> 2;
    int w = t >> 5, lane = t & 31, g = lane >> 2, tg = lane & 3;
    int st = w & 1, ch = w >> 1;

    // load concat [x | m1]
    for (int i = t; i < 64 * 256; i += 256) {
        int r = i >> 8, j = i & 255;
        size_t row = (size_t)b * NN + nb + r;
        float v = (j < 128) ? x[row * FIN + j] : g_m1[row * FOUT + (j - 128)];
        ts[r * TS_STRIDE + j] = v;
    }
    __syncthreads();

    // LN1 over 256
    float sum = 0, sq = 0;
#pragma unroll 8
    for (int i = 0; i < 64; i++) {
        float v = ts[nl * TS_STRIDE + cq * 64 + i];
        sum += v; sq += v * v;
    }
    sum = qsum(sum); sq = qsum(sq);
    float mu = sum * (1.0f / 256.0f);
    float rstd = rsqrtf(sq * (1.0f / 256.0f) - mu * mu + 1e-5f);
#pragma unroll 8
    for (int i = 0; i < 64; i++) {
        int j = cq * 64 + i;
        float v = ts[nl * TS_STRIDE + j];
        ts[nl * TS_STRIDE + j] = (v - mu) * rstd * ln1g[j] + ln1b[j];
    }

    float c[2][4][4];
    // mm1: m = LN1 @ linW + linb
    frag_zero(c);
    tail_mm(linW, ts, TS_STRIDE, 256, ws, c, st, ch, g, tg, t);
    frag_store(ms, MS_STRIDE, c, st, ch, g, tg);
    __syncthreads();
    float mreg[32];
#pragma unroll
    for (int d = 0; d < 32; d++) {
        int o = cq * 32 + d;
        mreg[d] = ms[nl * MS_STRIDE + o] + linb[o];
        ms[nl * MS_STRIDE + o] = mreg[d];
    }

    // mm2: u = gelu(m @ meW0 + meb0)
    frag_zero(c);
    tail_mm(meW0, ms, MS_STRIDE, 128, ws, c, st, ch, g, tg, t);
    frag_store(us, MS_STRIDE, c, st, ch, g, tg);
    __syncthreads();
#pragma unroll
    for (int d = 0; d < 32; d++) {
        int o = cq * 32 + d;
        us[nl * MS_STRIDE + o] = gelu_exact(us[nl * MS_STRIDE + o] + meb0[o]);
    }

    // mm3: enc = u @ meW1 + meb1; r = m + enc; LN2 -> us
    frag_zero(c);
    tail_mm(meW1, us, MS_STRIDE, 128, ws, c, st, ch, g, tg, t);
    frag_store(ts, TS_STRIDE, c, st, ch, g, tg);
    __syncthreads();
    float a3[32];
    sum = 0; sq = 0;
#pragma unroll
    for (int d = 0; d < 32; d++) {
        int o = cq * 32 + d;
        a3[d] = ts[nl * TS_STRIDE + o] + meb1[o] + mreg[d];
        sum += a3[d]; sq += a3[d] * a3[d];
    }
    sum = qsum(sum); sq = qsum(sq);
    mu = sum * (1.0f / 128.0f);
    rstd = rsqrtf(sq * (1.0f / 128.0f) - mu * mu + 1e-5f);
#pragma unroll
    for (int d = 0; d < 32; d++) {
        int o = cq * 32 + d;
        us[nl * MS_STRIDE + o] = (a3[d] - mu) * rstd * ln2g[o] + ln2b[o];
    }

    // mm4: v = gelu(us @ ohW + ohb); LN3; write out
    frag_zero(c);
    tail_mm(ohW, us, MS_STRIDE, 128, ws, c, st, ch, g, tg, t);
    frag_store(ts, TS_STRIDE, c, st, ch, g, tg);
    __syncthreads();
    float a4[32];
    sum = 0; sq = 0;
#pragma unroll
    for (int d = 0; d < 32; d++) {
        int o = cq * 32 + d;
        float v = gelu_exact(ts[nl * TS_STRIDE + o] + ohb[o]);
        a4[d] = v;
        sum += v; sq += v * v;
    }
    sum = qsum(sum); sq = qsum(sq);
    mu = sum * (1.0f / 128.0f);
    rstd = rsqrtf(sq * (1.0f / 128.0f) - mu * mu + 1e-5f);

    float* op = out + ((size_t)b * NN + nb + nl) * FOUT + cq * 32;
#pragma unroll
    for (int d4 = 0; d4 < 8; d4++) {
        float r0 = (a4[4 * d4 + 0] - mu) * rstd * ln3g[cq * 32 + 4 * d4 + 0] + ln3b[cq * 32 + 4 * d4 + 0];
        float r1 = (a4[4 * d4 + 1] - mu) * rstd * ln3g[cq * 32 + 4 * d4 + 1] + ln3b[cq * 32 + 4 * d4 + 1];
        float r2 = (a4[4 * d4 + 2] - mu) * rstd * ln3g[cq * 32 + 4 * d4 + 2] + ln3b[cq * 32 + 4 * d4 + 2];
        float r3 = (a4[4 * d4 + 3] - mu) * rstd * ln3g[cq * 32 + 4 * d4 + 3] + ln3b[cq * 32 + 4 * d4 + 3];
        ((float4*)op)[d4] = make_float4(r0, r1, r2, r3);
    }
}

// ------------------------- launch -------------------------
extern "C" void kernel_launch(void* const* d_in, const int* in_sizes, int n_in,
                              void* d_out, int out_size) {
    const float* x    = (const float*)d_in[0];
    const int*   grp  = (const int*)  d_in[1];
    const float* W0   = (const float*)d_in[2];
    const float* as0  = (const float*)d_in[3];
    const float* ad0  = (const float*)d_in[4];
    const float* W1   = (const float*)d_in[5];
    const float* as1  = (const float*)d_in[6];
    const float* ad1  = (const float*)d_in[7];
    const float* ln1g = (const float*)d_in[8];
    const float* ln1b = (const float*)d_in[9];
    const float* linW = (const float*)d_in[10];
    const float* linb = (const float*)d_in[11];
    const float* meW0 = (const float*)d_in[12];
    const float* meb0 = (const float*)d_in[13];
    const float* meW1 = (const float*)d_in[14];
    const float* meb1 = (const float*)d_in[15];
    const float* ln2g = (const float*)d_in[16];
    const float* ln2b = (const float*)d_in[17];
    const float* ohW  = (const float*)d_in[18];
    const float* ohb  = (const float*)d_in[19];
    const float* ln3g = (const float*)d_in[20];
    const float* ln3b = (const float*)d_in[21];
    float* out = (float*)d_out;

    cudaFuncSetAttribute(k_tail, cudaFuncAttributeMaxDynamicSharedMemorySize, TAIL_SMEM);
    cudaFuncSetAttribute(k_attn0_mma, cudaFuncAttributeMaxDynamicSharedMemorySize, A0_SMEM);
    cudaFuncSetAttribute(k_attn1_mma, cudaFuncAttributeMaxDynamicSharedMemorySize, A1_SMEM);
    cudaFuncSetAttribute(k_proj_mma<true>, cudaFuncAttributeMaxDynamicSharedMemorySize, PROJ_SMEM);
    cudaFuncSetAttribute(k_proj_mma<false>, cudaFuncAttributeMaxDynamicSharedMemorySize, PROJ_SMEM);

    k_mask<<<(BB * NN * NN) / 256, 256>>>(grp);
    k_proj_mma<true><<<dim3(NN / 128, BB), 256, PROJ_SMEM>>>(x, W0, as0, ad0);
    k_attn0_mma<<<dim3(NN / 64, BB), 256, A0_SMEM>>>();
    k_proj_mma<false><<<dim3(NN / 128, BB), 256, PROJ_SMEM>>>(nullptr, W1, as1, ad1);
    k_attn1_mma<<<dim3(NN / 64, BB), 256, A1_SMEM>>>();
    k_tail<<<dim3(NN / 64, BB), 256, TAIL_SMEM>>>(x, ln1g, ln1b, linW, linb,
                                                  meW0, meb0, meW1, meb1,
                                                  ln2g, ln2b, ohW, ohb,
                                                  ln3g, ln3b, out);
}

// round 5
// speedup vs baseline: 5.6695x; 1.2861x over previous
#include <cuda_runtime.h>
#include <math.h>

#define BB 32
#define NN 512
#define FIN 128
#define NH 4
#define FOUT 128
#define NW 16

// ------------------------- scratch (device globals; no allocation) -------------------------
// h0/h1/m0 live as tf32-bit, XOR-swizzled 64x128 tiles: elem (n, c) at
//   (b*NN + n)*128 + (c ^ ((n&3)<<3))
__device__ __align__(16) float    g_h0[(size_t)BB*NN*FIN];
__device__ float    g_s0[BB*NH*NN];
__device__ float    g_d0[BB*NH*NN];
__device__ __align__(16) float    g_m0[(size_t)BB*NN*FIN];
__device__ __align__(16) float    g_h1[(size_t)BB*NN*FOUT];
__device__ float    g_s1[BB*NN];
__device__ float    g_d1[BB*NN];
__device__ float    g_m1[(size_t)BB*NN*FOUT];   // fp32 row-major (tail reads scalar)
__device__ __align__(16) unsigned g_mask[BB*NN*NW];

// ------------------------- helpers -------------------------
__device__ __forceinline__ float qsum(float v) {
    v += __shfl_xor_sync(0xffffffffu, v, 1);
    v += __shfl_xor_sync(0xffffffffu, v, 2);
    return v;
}
__device__ __forceinline__ float lrelu(float z) { return z > 0.0f ? z : 0.2f * z; }
__device__ __forceinline__ float gelu_exact(float v) {
    return 0.5f * v * (1.0f + erff(v * 0.70710678118654752f));
}
__device__ __forceinline__ unsigned f2tf(float f) {
    unsigned u; asm("cvt.rna.tf32.f32 %0, %1;" : "=r"(u) : "f"(f)); return u;
}
__device__ __forceinline__ float tfh(float f) { return __uint_as_float(f2tf(f)); }
__device__ __forceinline__ void mma_tf32(float c[4], const unsigned a[4], const unsigned b[2]) {
    asm volatile("mma.sync.aligned.m16n8k8.row.col.f32.tf32.tf32.f32 "
                 "{%0,%1,%2,%3}, {%4,%5,%6,%7}, {%8,%9}, {%0,%1,%2,%3};"
                 : "+f"(c[0]), "+f"(c[1]), "+f"(c[2]), "+f"(c[3])
                 : "r"(a[0]), "r"(a[1]), "r"(a[2]), "r"(a[3]), "r"(b[0]), "r"(b[1]));
}
__device__ __forceinline__ unsigned sptr(const void* p) {
    return (unsigned)__cvta_generic_to_shared(p);
}
__device__ __forceinline__ void cpa16(unsigned s, const void* g) {
    asm volatile("cp.async.cg.shared.global [%0], [%1], 16;" :: "r"(s), "l"(g));
}
#define CP_COMMIT asm volatile("cp.async.commit_group;")
#define CP_WAIT(n) asm volatile("cp.async.wait_group %0;" :: "n"(n))

// issue raw 16B-chunk copy of a 64x128-float tile (layout preserved)
__device__ __forceinline__ void issue_tile(float* dst, const float* __restrict__ src, int t) {
    for (int i = t; i < 2048; i += 256) cpa16(sptr(dst + i * 4), src + i * 4);
}
// issue W 64x128 tile with XOR swizzle applied on 16B granularity
__device__ __forceinline__ void issue_wtile(float* dst, const float* __restrict__ src, int t) {
    for (int i = t; i < 2048; i += 256) {
        int r = i >> 5, c4 = (i & 31) * 4;
        cpa16(sptr(dst + r * 128 + (c4 ^ ((r & 3) << 3))), src + (size_t)r * 128 + c4);
    }
}

// ------------------------- kernel: adjacency -> bitmask -------------------------
__global__ void k_mask(const int* __restrict__ graph) {
    int idx = blockIdx.x * 256 + threadIdx.x;
    int m = idx & (NN - 1);
    int n = (idx >> 9) & (NN - 1);
    bool pred = (graph[idx] > 0) || (m == n);
    unsigned w = __ballot_sync(0xffffffffu, pred);
    if ((m & 31) == 0) g_mask[idx >> 5] = w;
}

// ------------------------- proj (mma): h = X@W [128x128x128 per CTA] + s/d logits ----------
#define PROJ_SMEM ((128*128 + 2*64*128 + 256) * 4)

template<bool MH>
__global__ __launch_bounds__(256, 1) void k_proj_mma(const float* __restrict__ Xin,
                                                     const float* __restrict__ Wg,
                                                     const float* __restrict__ av,
                                                     const float* __restrict__ bv) {
    extern __shared__ float sm[];
    float* xs = sm;                 // 128x128 tf32-bit swizzled A
    float* ws = xs + 128 * 128;     // 2 x (64x128) raw fp32 swizzled W
    float* sdb = ws + 2 * 64 * 128; // 256 accum for proj1 s/d

    int b = blockIdx.y, nb = blockIdx.x * 128;
    int t = threadIdx.x, w = t >> 5, lane = t & 31, g = lane >> 2, tg = lane & 3;
    int st = w & 3, ch = w >> 2;

    if (!MH) sdb[t] = 0.0f;

    // group0: (A if !MH) + W tile0;  group1: W tile1
    if (!MH) {
        const float* src = g_m0 + ((size_t)b * NN + nb) * 128;
        for (int i = t; i < 4096; i += 256) cpa16(sptr(xs + i * 4), src + i * 4);
    }
    issue_wtile(ws, Wg, t);
    CP_COMMIT;
    issue_wtile(ws + 8192, Wg + (size_t)64 * 128, t);
    CP_COMMIT;

    if (MH) {
        const float* src = Xin + ((size_t)b * NN + nb) * 128;
        for (int i = t; i < 128 * 32; i += 256) {
            int r = i >> 5, c4 = (i & 31) * 4;
            float4 v = *(const float4*)&src[(size_t)r * 128 + c4];
            float4 o; o.x = tfh(v.x); o.y = tfh(v.y); o.z = tfh(v.z); o.w = tfh(v.w);
            *(float4*)&xs[r * 128 + (c4 ^ ((r & 3) << 3))] = o;
        }
    }

    float c[2][8][4];
#pragma unroll
    for (int mf = 0; mf < 2; mf++)
#pragma unroll
        for (int j = 0; j < 8; j++)
#pragma unroll
            for (int e = 0; e < 4; e++) c[mf][j][e] = 0.0f;

#pragma unroll
    for (int kt = 0; kt < 2; kt++) {
        if (kt == 0) { CP_WAIT(1); } else { CP_WAIT(0); }
        __syncthreads();
        const float* wsb = ws + kt * 8192;
        for (int kc = 0; kc < 8; kc++) {
            unsigned a[2][4];
#pragma unroll
            for (int mf = 0; mf < 2; mf++) {
                int r = st * 32 + mf * 16 + g;
                int sw = (r & 3) << 3;
                int kb = kt * 64 + kc * 8;
                const float* xr = xs + r * 128;
                const float* xr8 = xs + (r + 8) * 128;
                a[mf][0] = __float_as_uint(xr[(kb + tg) ^ sw]);
                a[mf][1] = __float_as_uint(xr8[(kb + tg) ^ sw]);
                a[mf][2] = __float_as_uint(xr[(kb + tg + 4) ^ sw]);
                a[mf][3] = __float_as_uint(xr8[(kb + tg + 4) ^ sw]);
            }
            int k0 = kc * 8 + tg, k1 = k0 + 4;
            int sw0 = tg << 3;
#pragma unroll
            for (int j = 0; j < 8; j++) {
                int f = ch * 64 + j * 8 + g;
                unsigned bfr[2];
                bfr[0] = f2tf(wsb[k0 * 128 + (f ^ sw0)]);
                bfr[1] = f2tf(wsb[k1 * 128 + (f ^ sw0)]);
                mma_tf32(c[0][j], a[0], bfr);
                mma_tf32(c[1][j], a[1], bfr);
            }
        }
    }

    // write H as tf32 swizzled tiles
    float* H = MH ? (float*)g_h0 : (float*)g_h1;
#pragma unroll
    for (int mf = 0; mf < 2; mf++) {
        int row = st * 32 + mf * 16 + g;
        size_t base = ((size_t)b * NN + nb + row) * 128;
        int sw = (row & 3) << 3;
#pragma unroll
        for (int j = 0; j < 8; j++) {
            int col = (ch * 64 + j * 8 + 2 * tg) ^ sw;
            *(float2*)&H[base + col] = make_float2(tfh(c[mf][j][0]), tfh(c[mf][j][1]));
            *(float2*)&H[base + 8 * 128 + col] = make_float2(tfh(c[mf][j][2]), tfh(c[mf][j][3]));
        }
    }

    if (MH) {
        float sv[2][2][2], dv[2][2][2];
#pragma unroll
        for (int mf = 0; mf < 2; mf++)
#pragma unroll
            for (int hh = 0; hh < 2; hh++)
#pragma unroll
                for (int rr = 0; rr < 2; rr++) { sv[mf][hh][rr] = 0.0f; dv[mf][hh][rr] = 0.0f; }
#pragma unroll
        for (int mf = 0; mf < 2; mf++)
#pragma unroll
            for (int j = 0; j < 8; j++)
#pragma unroll
                for (int e = 0; e < 4; e++) {
                    int col = ch * 64 + j * 8 + 2 * tg + (e & 1);
                    sv[mf][j >> 2][e >> 1] += c[mf][j][e] * av[col];
                    dv[mf][j >> 2][e >> 1] += c[mf][j][e] * bv[col];
                }
#pragma unroll
        for (int mf = 0; mf < 2; mf++)
#pragma unroll
            for (int hh = 0; hh < 2; hh++)
#pragma unroll
                for (int rr = 0; rr < 2; rr++) {
                    sv[mf][hh][rr] = qsum(sv[mf][hh][rr]);
                    dv[mf][hh][rr] = qsum(dv[mf][hh][rr]);
                }
        if (tg == 0) {
#pragma unroll
            for (int mf = 0; mf < 2; mf++)
#pragma unroll
                for (int hh = 0; hh < 2; hh++)
#pragma unroll
                    for (int rr = 0; rr < 2; rr++) {
                        int r = st * 32 + mf * 16 + g + rr * 8;
                        int hidx = b * NH + 2 * ch + hh;
                        g_s0[hidx * NN + nb + r] = sv[mf][hh][rr];
                        g_d0[hidx * NN + nb + r] = dv[mf][hh][rr];
                    }
        }
    } else {
        float sv[2][2], dv[2][2];
#pragma unroll
        for (int mf = 0; mf < 2; mf++)
#pragma unroll
            for (int rr = 0; rr < 2; rr++) { sv[mf][rr] = 0.0f; dv[mf][rr] = 0.0f; }
#pragma unroll
        for (int mf = 0; mf < 2; mf++)
#pragma unroll
            for (int j = 0; j < 8; j++)
#pragma unroll
                for (int e = 0; e < 4; e++) {
                    int col = ch * 64 + j * 8 + 2 * tg + (e & 1);
                    sv[mf][e >> 1] += c[mf][j][e] * av[col];
                    dv[mf][e >> 1] += c[mf][j][e] * bv[col];
                }
#pragma unroll
        for (int mf = 0; mf < 2; mf++)
#pragma unroll
            for (int rr = 0; rr < 2; rr++) {
                sv[mf][rr] = qsum(sv[mf][rr]);
                dv[mf][rr] = qsum(dv[mf][rr]);
            }
        if (tg == 0) {
#pragma unroll
            for (int mf = 0; mf < 2; mf++)
#pragma unroll
                for (int rr = 0; rr < 2; rr++) {
                    int r = st * 32 + mf * 16 + g + rr * 8;
                    atomicAdd(&sdb[2 * r], sv[mf][rr]);
                    atomicAdd(&sdb[2 * r + 1], dv[mf][rr]);
                }
        }
        __syncthreads();
        if (t < 128) {
            g_s1[b * NN + nb + t] = sdb[2 * t];
            g_d1[b * NN + nb + t] = sdb[2 * t + 1];
        }
    }
}

// ------------------------- attn0: P-in-register flash mma, 4 heads, D=32 ----------------
// warps: h=w>>1, row-halves s0r=(w&1)*16; rows per warp: s0r+{g,g+8}, s0r+32+{g,g+8}
#define A0_SMEM ((2*64*128 + 4*512 + 64*16) * 4)

__global__ __launch_bounds__(256, 2) void k_attn0_mma() {
    extern __shared__ float sm[];
    float* sH = sm;                                   // 2 x 64x128 tf32 swizzled
    float* sd = sH + 2 * 8192;                        // 4 x 512
    unsigned long long* mkq = (unsigned long long*)(sd + 4 * 512);  // 64 x 8

    int b = blockIdx.y, nb = blockIdx.x * 64;
    int t = threadIdx.x, w = t >> 5, lane = t & 31, g = lane >> 2, tg = lane & 3;
    int h = w >> 1, s0r = (w & 1) * 16;

    const float* Hsrc = g_h0 + (size_t)b * NN * 128;
    issue_tile(sH, Hsrc, t);
    CP_COMMIT;

    for (int i = t; i < 2048; i += 256) sd[i] = g_d0[b * NH * NN + i];
    {
        const unsigned long long* gq =
            (const unsigned long long*)(g_mask + (size_t)(b * NN + nb) * NW);
        for (int i = t; i < 512; i += 256) mkq[i] = gq[i];
    }

    int rows[4] = { s0r + g, s0r + g + 8, s0r + 32 + g, s0r + 40 + g };
    float srow[4], S[4];
#pragma unroll
    for (int rr = 0; rr < 4; rr++) {
        srow[rr] = g_s0[(b * NH + h) * NN + nb + rows[rr]];
        S[rr] = 0.0f;
    }
    float c[2][4][4];
#pragma unroll
    for (int sp = 0; sp < 2; sp++)
#pragma unroll
        for (int j = 0; j < 4; j++)
#pragma unroll
            for (int e = 0; e < 4; e++) c[sp][j][e] = 0.0f;

    const float* dh = sd + h * 512;

    for (int mt = 0; mt < 8; mt++) {
        CP_WAIT(0);
        __syncthreads();
        if (mt + 1 < 8) {
            issue_tile(sH + ((mt + 1) & 1) * 8192, Hsrc + (size_t)(mt + 1) * 8192, t);
            CP_COMMIT;
        }
        const float* Hb = sH + (mt & 1) * 8192;
        unsigned long long mw[4];
#pragma unroll
        for (int rr = 0; rr < 4; rr++) mw[rr] = mkq[rows[rr] * 8 + mt];
        const float* dmt = dh + mt * 64;

#pragma unroll
        for (int kc = 0; kc < 8; kc++) {
            int c0 = kc * 8 + tg, c1 = c0 + 4;
            float d0 = dmt[c0], d1 = dmt[c1];
            int sw0 = tg << 3;
            unsigned bfr[4][2];
#pragma unroll
            for (int j = 0; j < 4; j++) {
                int f = h * 32 + j * 8 + g;
                bfr[j][0] = __float_as_uint(Hb[c0 * 128 + (f ^ sw0)]);
                bfr[j][1] = __float_as_uint(Hb[c1 * 128 + (f ^ sw0)]);
            }
#pragma unroll
            for (int sp = 0; sp < 2; sp++) {
                int r0 = sp * 2, r1 = sp * 2 + 1;
                float z0 = lrelu(srow[r0] + d0);
                float z1 = lrelu(srow[r1] + d0);
                float z2 = lrelu(srow[r0] + d1);
                float z3 = lrelu(srow[r1] + d1);
                float p0 = ((mw[r0] >> c0) & 1ull) ? __expf(z0) : 0.0f;
                float p1 = ((mw[r1] >> c0) & 1ull) ? __expf(z1) : 0.0f;
                float p2 = ((mw[r0] >> c1) & 1ull) ? __expf(z2) : 0.0f;
                float p3 = ((mw[r1] >> c1) & 1ull) ? __expf(z3) : 0.0f;
                S[r0] += p0 + p2;
                S[r1] += p1 + p3;
                unsigned a[4] = { f2tf(p0), f2tf(p1), f2tf(p2), f2tf(p3) };
#pragma unroll
                for (int j = 0; j < 4; j++) mma_tf32(c[sp][j], a, bfr[j]);
            }
        }
    }
#pragma unroll
    for (int rr = 0; rr < 4; rr++) S[rr] = qsum(S[rr]);

    // epilogue: /S, elu, tf32, swizzled write to g_m0
#pragma unroll
    for (int sp = 0; sp < 2; sp++) {
        float inv0 = 1.0f / S[sp * 2], inv1 = 1.0f / S[sp * 2 + 1];
        int r0 = s0r + sp * 32 + g;
        size_t base = ((size_t)b * NN + nb + r0) * 128;
        int sw = (r0 & 3) << 3;
#pragma unroll
        for (int j = 0; j < 4; j++) {
            int col = (h * 32 + j * 8 + 2 * tg) ^ sw;
            float v0 = c[sp][j][0] * inv0, v1 = c[sp][j][1] * inv0;
            float v2 = c[sp][j][2] * inv1, v3 = c[sp][j][3] * inv1;
            v0 = v0 > 0.0f ? v0 : expm1f(v0);
            v1 = v1 > 0.0f ? v1 : expm1f(v1);
            v2 = v2 > 0.0f ? v2 : expm1f(v2);
            v3 = v3 > 0.0f ? v3 : expm1f(v3);
            *(float2*)&g_m0[base + col] = make_float2(tfh(v0), tfh(v1));
            *(float2*)&g_m0[base + 8 * 128 + col] = make_float2(tfh(v2), tfh(v3));
        }
    }
}

// ------------------------- attn1: P-in-register mma, 1 head, D=128 ----------------------
// warps: st=w&3 (16-row stripe), ch=w>>2 (64-col half; exp duplicated x2)
#define A1_SMEM ((2*64*128 + 512 + 64*16) * 4)

__global__ __launch_bounds__(256, 2) void k_attn1_mma() {
    extern __shared__ float sm[];
    float* sH = sm;                      // 2 x 64x128
    float* sd = sH + 2 * 8192;           // 512
    unsigned long long* mkq = (unsigned long long*)(sd + 512);  // 64 x 8

    int b = blockIdx.y, nb = blockIdx.x * 64;
    int t = threadIdx.x, w = t >> 5, lane = t & 31, g = lane >> 2, tg = lane & 3;
    int st = w & 3, ch = w >> 2;

    const float* Hsrc = g_h1 + (size_t)b * NN * 128;
    issue_tile(sH, Hsrc, t);
    CP_COMMIT;

    for (int i = t; i < 512; i += 256) sd[i] = g_d1[b * NN + i];
    {
        const unsigned long long* gq =
            (const unsigned long long*)(g_mask + (size_t)(b * NN + nb) * NW);
        for (int i = t; i < 512; i += 256) mkq[i] = gq[i];
    }

    int r0 = st * 16 + g, r1 = r0 + 8;
    float s0v = g_s1[b * NN + nb + r0];
    float s1v = g_s1[b * NN + nb + r1];
    float S0 = 0.0f, S1 = 0.0f;
    float c[8][4];
#pragma unroll
    for (int j = 0; j < 8; j++)
#pragma unroll
        for (int e = 0; e < 4; e++) c[j][e] = 0.0f;

    for (int mt = 0; mt < 8; mt++) {
        CP_WAIT(0);
        __syncthreads();
        if (mt + 1 < 8) {
            issue_tile(sH + ((mt + 1) & 1) * 8192, Hsrc + (size_t)(mt + 1) * 8192, t);
            CP_COMMIT;
        }
        const float* Hb = sH + (mt & 1) * 8192;
        unsigned long long mw0 = mkq[r0 * 8 + mt];
        unsigned long long mw1 = mkq[r1 * 8 + mt];
        const float* dmt = sd + mt * 64;

#pragma unroll
        for (int kc = 0; kc < 8; kc++) {
            int c0 = kc * 8 + tg, c1 = c0 + 4;
            float d0 = dmt[c0], d1 = dmt[c1];
            float z0 = lrelu(s0v + d0);
            float z1 = lrelu(s1v + d0);
            float z2 = lrelu(s0v + d1);
            float z3 = lrelu(s1v + d1);
            float p0 = ((mw0 >> c0) & 1ull) ? __expf(z0) : 0.0f;
            float p1 = ((mw1 >> c0) & 1ull) ? __expf(z1) : 0.0f;
            float p2 = ((mw0 >> c1) & 1ull) ? __expf(z2) : 0.0f;
            float p3 = ((mw1 >> c1) & 1ull) ? __expf(z3) : 0.0f;
            S0 += p0 + p2;
            S1 += p1 + p3;
            unsigned a[4] = { f2tf(p0), f2tf(p1), f2tf(p2), f2tf(p3) };
            int sw0 = tg << 3;
#pragma unroll
            for (int j = 0; j < 8; j++) {
                int f = ch * 64 + j * 8 + g;
                unsigned bfr[2];
                bfr[0] = __float_as_uint(Hb[c0 * 128 + (f ^ sw0)]);
                bfr[1] = __float_as_uint(Hb[c1 * 128 + (f ^ sw0)]);
                mma_tf32(c[j], a, bfr);
            }
        }
    }
    S0 = qsum(S0); S1 = qsum(S1);
    float inv0 = 1.0f / S0, inv1 = 1.0f / S1;
    size_t base = ((size_t)b * NN + nb + r0) * 128;
#pragma unroll
    for (int j = 0; j < 8; j++) {
        int col = ch * 64 + j * 8 + 2 * tg;
        *(float2*)&g_m1[base + col] = make_float2(c[j][0] * inv0, c[j][1] * inv0);
        *(float2*)&g_m1[base + 8 * 128 + col] = make_float2(c[j][2] * inv1, c[j][3] * inv1);
    }
}

// ------------------------- fused tail (mma + cp.async weight pipeline) -------------------
#define TS_STRIDE 260
#define MS_STRIDE 132
#define TAIL_SMEM ((64*TS_STRIDE + 2*64*MS_STRIDE + 2*64*128) * 4)

__device__ __forceinline__ void tail_mm(const float* __restrict__ Wg, const float* A,
                                        int astride, int K, float* ws, float c[2][4][4],
                                        int st, int ch, int g, int tg, int t) {
    issue_wtile(ws, Wg, t);
    CP_COMMIT;
    int NS = K >> 6;
    for (int kt = 0; kt < NS; kt++) {
        CP_WAIT(0);
        __syncthreads();
        if (kt + 1 < NS) {
            issue_wtile(ws + ((kt + 1) & 1) * 8192, Wg + (size_t)(kt + 1) * 8192, t);
            CP_COMMIT;
        }
        const float* wsb = ws + (kt & 1) * 8192;
        for (int kc = 0; kc < 8; kc++) {
            unsigned a[2][4];
#pragma unroll
            for (int mf = 0; mf < 2; mf++) {
                const float* pr = A + (st * 32 + mf * 16 + g) * astride + kt * 64 + kc * 8;
                a[mf][0] = f2tf(pr[tg]);
                a[mf][1] = f2tf(pr[8 * astride + tg]);
                a[mf][2] = f2tf(pr[tg + 4]);
                a[mf][3] = f2tf(pr[8 * astride + tg + 4]);
            }
            int k0 = kc * 8 + tg, k1 = k0 + 4;
            int sw0 = tg << 3;
#pragma unroll
            for (int j = 0; j < 4; j++) {
                int f = ch * 32 + j * 8 + g;
                unsigned bfr[2];
                bfr[0] = f2tf(wsb[k0 * 128 + (f ^ sw0)]);
                bfr[1] = f2tf(wsb[k1 * 128 + (f ^ sw0)]);
                mma_tf32(c[0][j], a[0], bfr);
                mma_tf32(c[1][j], a[1], bfr);
            }
        }
    }
}

__device__ __forceinline__ void frag_store(float* D, int dstride, float c[2][4][4],
                                           int st, int ch, int g, int tg) {
#pragma unroll
    for (int mf = 0; mf < 2; mf++) {
        int row = st * 32 + mf * 16 + g;
#pragma unroll
        for (int j = 0; j < 4; j++) {
            int col = ch * 32 + j * 8 + 2 * tg;
            *(float2*)&D[row * dstride + col] = make_float2(c[mf][j][0], c[mf][j][1]);
            *(float2*)&D[(row + 8) * dstride + col] = make_float2(c[mf][j][2], c[mf][j][3]);
        }
    }
}

__device__ __forceinline__ void frag_zero(float c[2][4][4]) {
#pragma unroll
    for (int mf = 0; mf < 2; mf++)
#pragma unroll
        for (int j = 0; j < 4; j++)
#pragma unroll
            for (int e = 0; e < 4; e++) c[mf][j][e] = 0.0f;
}

__global__ __launch_bounds__(256, 1) void k_tail(const float* __restrict__ x,
                       const float* __restrict__ ln1g, const float* __restrict__ ln1b,
                       const float* __restrict__ linW, const float* __restrict__ linb,
                       const float* __restrict__ meW0, const float* __restrict__ meb0,
                       const float* __restrict__ meW1, const float* __restrict__ meb1,
                       const float* __restrict__ ln2g, const float* __restrict__ ln2b,
                       const float* __restrict__ ohW, const float* __restrict__ ohb,
                       const float* __restrict__ ln3g, const float* __restrict__ ln3b,
                       float* __restrict__ out) {
    extern __shared__ float sm[];
    float* ts = sm;                      // 64 x 260
    float* ms = ts + 64 * TS_STRIDE;     // 64 x 132
    float* us = ms + 64 * MS_STRIDE;     // 64 x 132
    float* ws = us + 64 * MS_STRIDE;     // 2 x 64x128 weight pipeline

    int b = blockIdx.y, nb = blockIdx.x * 64;
    int t = threadIdx.x, cq = t & 3, nl = t >> 2;
    int w = t >> 5, lane = t & 31, g = lane >> 2, tg = lane & 3;
    int st = w & 1, ch = w >> 1;

    for (int i = t; i < 64 * 256; i += 256) {
        int r = i >> 8, j = i & 255;
        size_t row = (size_t)b * NN + nb + r;
        float v = (j < 128) ? x[row * FIN + j] : g_m1[row * FOUT + (j - 128)];
        ts[r * TS_STRIDE + j] = v;
    }
    __syncthreads();

    float sum = 0, sq = 0;
#pragma unroll 8
    for (int i = 0; i < 64; i++) {
        float v = ts[nl * TS_STRIDE + cq * 64 + i];
        sum += v; sq += v * v;
    }
    sum = qsum(sum); sq = qsum(sq);
    float mu = sum * (1.0f / 256.0f);
    float rstd = rsqrtf(sq * (1.0f / 256.0f) - mu * mu + 1e-5f);
#pragma unroll 8
    for (int i = 0; i < 64; i++) {
        int j = cq * 64 + i;
        float v = ts[nl * TS_STRIDE + j];
        ts[nl * TS_STRIDE + j] = (v - mu) * rstd * ln1g[j] + ln1b[j];
    }

    float c[2][4][4];
    // mm1
    frag_zero(c);
    tail_mm(linW, ts, TS_STRIDE, 256, ws, c, st, ch, g, tg, t);
    frag_store(ms, MS_STRIDE, c, st, ch, g, tg);
    __syncthreads();
    float mreg[32];
#pragma unroll
    for (int d = 0; d < 32; d++) {
        int o = cq * 32 + d;
        mreg[d] = ms[nl * MS_STRIDE + o] + linb[o];
        ms[nl * MS_STRIDE + o] = mreg[d];
    }

    // mm2
    frag_zero(c);
    tail_mm(meW0, ms, MS_STRIDE, 128, ws, c, st, ch, g, tg, t);
    frag_store(us, MS_STRIDE, c, st, ch, g, tg);
    __syncthreads();
#pragma unroll
    for (int d = 0; d < 32; d++) {
        int o = cq * 32 + d;
        us[nl * MS_STRIDE + o] = gelu_exact(us[nl * MS_STRIDE + o] + meb0[o]);
    }

    // mm3 + LN2
    frag_zero(c);
    tail_mm(meW1, us, MS_STRIDE, 128, ws, c, st, ch, g, tg, t);
    frag_store(ts, TS_STRIDE, c, st, ch, g, tg);
    __syncthreads();
    float a3[32];
    sum = 0; sq = 0;
#pragma unroll
    for (int d = 0; d < 32; d++) {
        int o = cq * 32 + d;
        a3[d] = ts[nl * TS_STRIDE + o] + meb1[o] + mreg[d];
        sum += a3[d]; sq += a3[d] * a3[d];
    }
    sum = qsum(sum); sq = qsum(sq);
    mu = sum * (1.0f / 128.0f);
    rstd = rsqrtf(sq * (1.0f / 128.0f) - mu * mu + 1e-5f);
#pragma unroll
    for (int d = 0; d < 32; d++) {
        int o = cq * 32 + d;
        us[nl * MS_STRIDE + o] = (a3[d] - mu) * rstd * ln2g[o] + ln2b[o];
    }

    // mm4 + gelu + LN3
    frag_zero(c);
    tail_mm(ohW, us, MS_STRIDE, 128, ws, c, st, ch, g, tg, t);
    frag_store(ts, TS_STRIDE, c, st, ch, g, tg);
    __syncthreads();
    float a4[32];
    sum = 0; sq = 0;
#pragma unroll
    for (int d = 0; d < 32; d++) {
        int o = cq * 32 + d;
        float v = gelu_exact(ts[nl * TS_STRIDE + o] + ohb[o]);
        a4[d] = v;
        sum += v; sq += v * v;
    }
    sum = qsum(sum); sq = qsum(sq);
    mu = sum * (1.0f / 128.0f);
    rstd = rsqrtf(sq * (1.0f / 128.0f) - mu * mu + 1e-5f);

    float* op = out + ((size_t)b * NN + nb + nl) * FOUT + cq * 32;
#pragma unroll
    for (int d4 = 0; d4 < 8; d4++) {
        float r0 = (a4[4 * d4 + 0] - mu) * rstd * ln3g[cq * 32 + 4 * d4 + 0] + ln3b[cq * 32 + 4 * d4 + 0];
        float r1 = (a4[4 * d4 + 1] - mu) * rstd * ln3g[cq * 32 + 4 * d4 + 1] + ln3b[cq * 32 + 4 * d4 + 1];
        float r2 = (a4[4 * d4 + 2] - mu) * rstd * ln3g[cq * 32 + 4 * d4 + 2] + ln3b[cq * 32 + 4 * d4 + 2];
        float r3 = (a4[4 * d4 + 3] - mu) * rstd * ln3g[cq * 32 + 4 * d4 + 3] + ln3b[cq * 32 + 4 * d4 + 3];
        ((float4*)op)[d4] = make_float4(r0, r1, r2, r3);
    }
}

// ------------------------- launch -------------------------
extern "C" void kernel_launch(void* const* d_in, const int* in_sizes, int n_in,
                              void* d_out, int out_size) {
    const float* x    = (const float*)d_in[0];
    const int*   grp  = (const int*)  d_in[1];
    const float* W0   = (const float*)d_in[2];
    const float* as0  = (const float*)d_in[3];
    const float* ad0  = (const float*)d_in[4];
    const float* W1   = (const float*)d_in[5];
    const float* as1  = (const float*)d_in[6];
    const float* ad1  = (const float*)d_in[7];
    const float* ln1g = (const float*)d_in[8];
    const float* ln1b = (const float*)d_in[9];
    const float* linW = (const float*)d_in[10];
    const float* linb = (const float*)d_in[11];
    const float* meW0 = (const float*)d_in[12];
    const float* meb0 = (const float*)d_in[13];
    const float* meW1 = (const float*)d_in[14];
    const float* meb1 = (const float*)d_in[15];
    const float* ln2g = (const float*)d_in[16];
    const float* ln2b = (const float*)d_in[17];
    const float* ohW  = (const float*)d_in[18];
    const float* ohb  = (const float*)d_in[19];
    const float* ln3g = (const float*)d_in[20];
    const float* ln3b = (const float*)d_in[21];
    float* out = (float*)d_out;

    cudaFuncSetAttribute(k_tail, cudaFuncAttributeMaxDynamicSharedMemorySize, TAIL_SMEM);
    cudaFuncSetAttribute(k_attn0_mma, cudaFuncAttributeMaxDynamicSharedMemorySize, A0_SMEM);
    cudaFuncSetAttribute(k_attn1_mma, cudaFuncAttributeMaxDynamicSharedMemorySize, A1_SMEM);
    cudaFuncSetAttribute(k_proj_mma<true>, cudaFuncAttributeMaxDynamicSharedMemorySize, PROJ_SMEM);
    cudaFuncSetAttribute(k_proj_mma<false>, cudaFuncAttributeMaxDynamicSharedMemorySize, PROJ_SMEM);

    k_mask<<<(BB * NN * NN) / 256, 256>>>(grp);
    k_proj_mma<true><<<dim3(NN / 128, BB), 256, PROJ_SMEM>>>(x, W0, as0, ad0);
    k_attn0_mma<<<dim3(NN / 64, BB), 256, A0_SMEM>>>();
    k_proj_mma<false><<<dim3(NN / 128, BB), 256, PROJ_SMEM>>>(nullptr, W1, as1, ad1);
    k_attn1_mma<<<dim3(NN / 64, BB), 256, A1_SMEM>>>();
    k_tail<<<dim3(NN / 64, BB), 256, TAIL_SMEM>>>(x, ln1g, ln1b, linW, linb,
                                                  meW0, meb0, meW1, meb1,
                                                  ln2g, ln2b, ohW, ohb,
                                                  ln3g, ln3b, out);
}

// round 6
// speedup vs baseline: 6.7941x; 1.1984x over previous
#include <cuda_runtime.h>
#include <math.h>

#define BB 32
#define NN 512
#define NH 4
#define NW 16
#define LOG2E 1.4426950408889634f

// ------------------------- scratch (device globals; no allocation) -------------------------
// h0/h1 live as tf32-bit, XOR-swizzled 64x128 tiles: elem (n, c) at
//   (b*NN + n)*128 + (c ^ ((n&3)<<3))
__device__ __align__(16) float    g_h0[(size_t)BB*NN*128];
__device__ float    g_s0[BB*NH*NN];   // pre-scaled by log2e
__device__ float    g_d0[BB*NH*NN];
__device__ __align__(16) float    g_h1[(size_t)BB*NN*128];
__device__ float    g_s1[BB*NN];      // pre-scaled by log2e
__device__ float    g_d1[BB*NN];
__device__ float    g_m1[(size_t)BB*NN*128];  // fp32 row-major
__device__ __align__(16) unsigned g_mask[BB*NN*NW];

// ------------------------- helpers -------------------------
__device__ __forceinline__ float qsum(float v) {
    v += __shfl_xor_sync(0xffffffffu, v, 1);
    v += __shfl_xor_sync(0xffffffffu, v, 2);
    return v;
}
__device__ __forceinline__ float gelu_exact(float v) {
    return 0.5f * v * (1.0f + erff(v * 0.70710678118654752f));
}
__device__ __forceinline__ unsigned f2tf(float f) {
    unsigned u; asm("cvt.rna.tf32.f32 %0, %1;" : "=r"(u) : "f"(f)); return u;
}
__device__ __forceinline__ float tfh(float f) { return __uint_as_float(f2tf(f)); }
__device__ __forceinline__ float ex2f(float x) {
    float y; asm("ex2.approx.f32 %0, %1;" : "=f"(y) : "f"(x)); return y;
}
__device__ __forceinline__ void mma_tf32(float c[4], const unsigned a[4], const unsigned b[2]) {
    asm volatile("mma.sync.aligned.m16n8k8.row.col.f32.tf32.tf32.f32 "
                 "{%0,%1,%2,%3}, {%4,%5,%6,%7}, {%8,%9}, {%0,%1,%2,%3};"
                 : "+f"(c[0]), "+f"(c[1]), "+f"(c[2]), "+f"(c[3])
                 : "r"(a[0]), "r"(a[1]), "r"(a[2]), "r"(a[3]), "r"(b[0]), "r"(b[1]));
}
__device__ __forceinline__ unsigned sptr(const void* p) {
    return (unsigned)__cvta_generic_to_shared(p);
}
__device__ __forceinline__ void cpa16(unsigned s, const void* g) {
    asm volatile("cp.async.cg.shared.global [%0], [%1], 16;" :: "r"(s), "l"(g));
}
#define CP_COMMIT asm volatile("cp.async.commit_group;")
#define CP_WAIT(n) asm volatile("cp.async.wait_group %0;" :: "n"(n))

// raw 16B-chunk copy of a 64x128-float tile (layout preserved)
__device__ __forceinline__ void issue_tile(float* dst, const float* __restrict__ src, int t) {
    for (int i = t; i < 2048; i += 256) cpa16(sptr(dst + i * 4), src + i * 4);
}
// 64x128 tile with XOR swizzle applied on 16B granularity
__device__ __forceinline__ void issue_wtile(float* dst, const float* __restrict__ src, int t) {
    for (int i = t; i < 2048; i += 256) {
        int r = i >> 5, c4 = (i & 31) * 4;
        cpa16(sptr(dst + r * 128 + (c4 ^ ((r & 3) << 3))), src + (size_t)r * 128 + c4);
    }
}

// ------------------------- proj0: h0 = X@W0 (64x128x128 per CTA) + s0/d0 -------------------
// 8 warps: st=w&1 (32-row stripe), ch=w>>1 (32-col quarter == head ch)
#define P0_SMEM ((64*128 + 2*64*128) * 4)

__global__ __launch_bounds__(256, 2) void k_proj0(const float* __restrict__ x,
                                                  const float* __restrict__ Wg,
                                                  const float* __restrict__ av,
                                                  const float* __restrict__ bv) {
    extern __shared__ float sm[];
    float* xs = sm;            // 64x128 raw fp32 swizzled A
    float* ws = xs + 8192;     // 2 x 64x128 raw fp32 swizzled W

    int b = blockIdx.y, nb = blockIdx.x * 64;
    int t = threadIdx.x, w = t >> 5, lane = t & 31, g = lane >> 2, tg = lane & 3;
    int st = w & 1, ch = w >> 1;

    issue_wtile(xs, x + ((size_t)b * NN + nb) * 128, t);
    issue_wtile(ws, Wg, t);
    CP_COMMIT;
    issue_wtile(ws + 8192, Wg + 8192, t);
    CP_COMMIT;

    float c[2][4][4];
#pragma unroll
    for (int mf = 0; mf < 2; mf++)
#pragma unroll
        for (int j = 0; j < 4; j++)
#pragma unroll
            for (int e = 0; e < 4; e++) c[mf][j][e] = 0.0f;

#pragma unroll
    for (int kt = 0; kt < 2; kt++) {
        if (kt == 0) { CP_WAIT(1); } else { CP_WAIT(0); }
        __syncthreads();
        const float* wsb = ws + kt * 8192;
        for (int kc = 0; kc < 8; kc++) {
            unsigned a[2][4];
#pragma unroll
            for (int mf = 0; mf < 2; mf++) {
                int r = st * 32 + mf * 16 + g;
                int sw = (r & 3) << 3;
                int kb = kt * 64 + kc * 8;
                a[mf][0] = f2tf(xs[r * 128 + ((kb + tg) ^ sw)]);
                a[mf][1] = f2tf(xs[(r + 8) * 128 + ((kb + tg) ^ sw)]);
                a[mf][2] = f2tf(xs[r * 128 + ((kb + tg + 4) ^ sw)]);
                a[mf][3] = f2tf(xs[(r + 8) * 128 + ((kb + tg + 4) ^ sw)]);
            }
            int k0 = kc * 8 + tg, k1 = k0 + 4;
            int sw0 = tg << 3;
#pragma unroll
            for (int j = 0; j < 4; j++) {
                int f = ch * 32 + j * 8 + g;
                unsigned bfr[2];
                bfr[0] = f2tf(wsb[k0 * 128 + (f ^ sw0)]);
                bfr[1] = f2tf(wsb[k1 * 128 + (f ^ sw0)]);
                mma_tf32(c[0][j], a[0], bfr);
                mma_tf32(c[1][j], a[1], bfr);
            }
        }
    }

    // h0 write (tf32 swizzled)
#pragma unroll
    for (int mf = 0; mf < 2; mf++) {
        int row = st * 32 + mf * 16 + g;
        size_t base = ((size_t)b * NN + nb + row) * 128;
        int sw = (row & 3) << 3;
#pragma unroll
        for (int j = 0; j < 4; j++) {
            int col = (ch * 32 + j * 8 + 2 * tg) ^ sw;
            *(float2*)&g_h0[base + col] = make_float2(tfh(c[mf][j][0]), tfh(c[mf][j][1]));
            *(float2*)&g_h0[base + 8 * 128 + col] = make_float2(tfh(c[mf][j][2]), tfh(c[mf][j][3]));
        }
    }

    // s0/d0 (head == ch), pre-scaled by log2e
    float sv[2][2], dv[2][2];
#pragma unroll
    for (int mf = 0; mf < 2; mf++)
#pragma unroll
        for (int rr = 0; rr < 2; rr++) { sv[mf][rr] = 0.0f; dv[mf][rr] = 0.0f; }
#pragma unroll
    for (int mf = 0; mf < 2; mf++)
#pragma unroll
        for (int j = 0; j < 4; j++)
#pragma unroll
            for (int e = 0; e < 4; e++) {
                int col = ch * 32 + j * 8 + 2 * tg + (e & 1);
                sv[mf][e >> 1] += c[mf][j][e] * av[col];
                dv[mf][e >> 1] += c[mf][j][e] * bv[col];
            }
#pragma unroll
    for (int mf = 0; mf < 2; mf++)
#pragma unroll
        for (int rr = 0; rr < 2; rr++) {
            sv[mf][rr] = qsum(sv[mf][rr]);
            dv[mf][rr] = qsum(dv[mf][rr]);
        }
    if (tg == 0) {
#pragma unroll
        for (int mf = 0; mf < 2; mf++)
#pragma unroll
            for (int rr = 0; rr < 2; rr++) {
                int r = st * 32 + mf * 16 + g + rr * 8;
                g_s0[(b * NH + ch) * NN + nb + r] = sv[mf][rr] * LOG2E;
                g_d0[(b * NH + ch) * NN + nb + r] = dv[mf][rr] * LOG2E;
            }
    }
}

// ------------------------- attn0 fused: mask-gen + GAT0 softmax-agg + ELU + proj1 ----------
// attn warps: h=w>>1, s0r=(w&1)*16. proj warps: st2=w&1, ch2=w>>1.
#define A0_SMEM ((2*8192 + 2048 + 1024 + 8192 + 128) * 4)

__global__ __launch_bounds__(256, 2) void k_attn0(const int* __restrict__ graph,
                                                  const float* __restrict__ W1,
                                                  const float* __restrict__ av,
                                                  const float* __restrict__ bv) {
    extern __shared__ float sm[];
    float* sH = sm;                                // 2 x 64x128 (H tiles, later W1 tiles)
    float* sd = sH + 16384;                        // 4 x 512 d0
    unsigned* mk32 = (unsigned*)(sd + 2048);       // 1024 mask words
    float* xm = (float*)(mk32 + 1024);             // 64x128 m0 tile (tf32 swizzled)
    float* sdb = xm + 8192;                        // 128 (s1/d1 accum)

    int b = blockIdx.y, nb = blockIdx.x * 64;
    int t = threadIdx.x, w = t >> 5, lane = t & 31, g = lane >> 2, tg = lane & 3;
    int h = w >> 1, s0r = (w & 1) * 16;

    const float* Hsrc = g_h0 + (size_t)b * NN * 128;
    issue_tile(sH, Hsrc, t);
    CP_COMMIT;

    if (t < 128) sdb[t] = 0.0f;

    // mask generation for rows nb..nb+63 (ballot over graph)
    for (int wi = w; wi < 1024; wi += 8) {
        int row = wi >> 4, mq = wi & 15;
        int m = mq * 32 + lane, gn = nb + row;
        bool pred = (graph[((size_t)b * NN + gn) * NN + m] > 0) || (gn == m);
        unsigned bits = __ballot_sync(0xffffffffu, pred);
        if (lane == 0) mk32[wi] = bits;
    }
    for (int i = t; i < 2048; i += 256) sd[i] = g_d0[b * NH * NN + i];
    __syncthreads();
    // publish masks for attn1
    ((uint4*)(g_mask + (size_t)(b * NN + nb) * NW))[t] = ((uint4*)mk32)[t];

    const unsigned long long* mkq = (const unsigned long long*)mk32;

    int rows[4] = { s0r + g, s0r + g + 8, s0r + 32 + g, s0r + 40 + g };
    float srow[4], S[4];
#pragma unroll
    for (int rr = 0; rr < 4; rr++) {
        srow[rr] = g_s0[(b * NH + h) * NN + nb + rows[rr]];
        S[rr] = 0.0f;
    }
    float c[2][4][4];
#pragma unroll
    for (int sp = 0; sp < 2; sp++)
#pragma unroll
        for (int j = 0; j < 4; j++)
#pragma unroll
            for (int e = 0; e < 4; e++) c[sp][j][e] = 0.0f;

    const float* dh = sd + h * 512;

    for (int mt = 0; mt < 8; mt++) {
        CP_WAIT(0);
        __syncthreads();
        if (mt + 1 < 8) {
            issue_tile(sH + ((mt + 1) & 1) * 8192, Hsrc + (size_t)(mt + 1) * 8192, t);
            CP_COMMIT;
        } else {
            issue_wtile(sH, W1, t);   // sH[0] free during mt=7 (reads sH[1])
            CP_COMMIT;
        }
        const float* Hb = sH + (mt & 1) * 8192;
        unsigned long long mw[4];
#pragma unroll
        for (int rr = 0; rr < 4; rr++) mw[rr] = mkq[rows[rr] * 8 + mt];
        const float* dmt = dh + mt * 64;

#pragma unroll
        for (int kc = 0; kc < 8; kc++) {
            int c0 = kc * 8 + tg, c1 = c0 + 4;
            float d0 = dmt[c0], d1 = dmt[c1];
            int sw0 = tg << 3;
            unsigned bfr[4][2];
#pragma unroll
            for (int j = 0; j < 4; j++) {
                int f = h * 32 + j * 8 + g;
                bfr[j][0] = __float_as_uint(Hb[c0 * 128 + (f ^ sw0)]);
                bfr[j][1] = __float_as_uint(Hb[c1 * 128 + (f ^ sw0)]);
            }
#pragma unroll
            for (int sp = 0; sp < 2; sp++) {
                int r0 = sp * 2, r1 = sp * 2 + 1;
                float z0 = srow[r0] + d0, z1 = srow[r1] + d0;
                float z2 = srow[r0] + d1, z3 = srow[r1] + d1;
                float p0 = ((mw[r0] >> c0) & 1ull) ? ex2f(fmaxf(z0, 0.2f * z0)) : 0.0f;
                float p1 = ((mw[r1] >> c0) & 1ull) ? ex2f(fmaxf(z1, 0.2f * z1)) : 0.0f;
                float p2 = ((mw[r0] >> c1) & 1ull) ? ex2f(fmaxf(z2, 0.2f * z2)) : 0.0f;
                float p3 = ((mw[r1] >> c1) & 1ull) ? ex2f(fmaxf(z3, 0.2f * z3)) : 0.0f;
                S[r0] += p0 + p2;
                S[r1] += p1 + p3;
                unsigned a[4] = { f2tf(p0), f2tf(p1), f2tf(p2), f2tf(p3) };
#pragma unroll
                for (int j = 0; j < 4; j++) mma_tf32(c[sp][j], a, bfr[j]);
            }
        }
    }
#pragma unroll
    for (int rr = 0; rr < 4; rr++) S[rr] = qsum(S[rr]);

    // m0 epilogue: /S, elu, tf32, into smem xm (swizzled)
#pragma unroll
    for (int sp = 0; sp < 2; sp++) {
        float inv0 = 1.0f / S[sp * 2], inv1 = 1.0f / S[sp * 2 + 1];
        int r0 = s0r + sp * 32 + g;
        int sw = (r0 & 3) << 3;
#pragma unroll
        for (int j = 0; j < 4; j++) {
            int col = (h * 32 + j * 8 + 2 * tg) ^ sw;
            float v0 = c[sp][j][0] * inv0, v1 = c[sp][j][1] * inv0;
            float v2 = c[sp][j][2] * inv1, v3 = c[sp][j][3] * inv1;
            v0 = v0 > 0.0f ? v0 : expm1f(v0);
            v1 = v1 > 0.0f ? v1 : expm1f(v1);
            v2 = v2 > 0.0f ? v2 : expm1f(v2);
            v3 = v3 > 0.0f ? v3 : expm1f(v3);
            *(float2*)&xm[r0 * 128 + col] = make_float2(tfh(v0), tfh(v1));
            *(float2*)&xm[(r0 + 8) * 128 + col] = make_float2(tfh(v2), tfh(v3));
        }
    }
    __syncthreads();                      // xm complete; sH[1] free
    issue_wtile(sH + 8192, W1 + 8192, t);
    CP_COMMIT;

    // ---- fused proj1: h1 = m0 @ W1, 64x128x128 ----
    int st2 = w & 1, ch2 = w >> 1;
    float c2[2][4][4];
#pragma unroll
    for (int mf = 0; mf < 2; mf++)
#pragma unroll
        for (int j = 0; j < 4; j++)
#pragma unroll
            for (int e = 0; e < 4; e++) c2[mf][j][e] = 0.0f;

#pragma unroll
    for (int kt = 0; kt < 2; kt++) {
        if (kt == 0) { CP_WAIT(1); } else { CP_WAIT(0); }
        __syncthreads();
        const float* wsb = sH + kt * 8192;
        for (int kc = 0; kc < 8; kc++) {
            unsigned a[2][4];
#pragma unroll
            for (int mf = 0; mf < 2; mf++) {
                int r = st2 * 32 + mf * 16 + g;
                int sw = (r & 3) << 3;
                int kb = kt * 64 + kc * 8;
                a[mf][0] = __float_as_uint(xm[r * 128 + ((kb + tg) ^ sw)]);
                a[mf][1] = __float_as_uint(xm[(r + 8) * 128 + ((kb + tg) ^ sw)]);
                a[mf][2] = __float_as_uint(xm[r * 128 + ((kb + tg + 4) ^ sw)]);
                a[mf][3] = __float_as_uint(xm[(r + 8) * 128 + ((kb + tg + 4) ^ sw)]);
            }
            int k0 = kc * 8 + tg, k1 = k0 + 4;
            int sw0 = tg << 3;
#pragma unroll
            for (int j = 0; j < 4; j++) {
                int f = ch2 * 32 + j * 8 + g;
                unsigned bfr[2];
                bfr[0] = f2tf(wsb[k0 * 128 + (f ^ sw0)]);
                bfr[1] = f2tf(wsb[k1 * 128 + (f ^ sw0)]);
                mma_tf32(c2[0][j], a[0], bfr);
                mma_tf32(c2[1][j], a[1], bfr);
            }
        }
    }

    // h1 write (tf32 swizzled)
#pragma unroll
    for (int mf = 0; mf < 2; mf++) {
        int row = st2 * 32 + mf * 16 + g;
        size_t base = ((size_t)b * NN + nb + row) * 128;
        int sw = (row & 3) << 3;
#pragma unroll
        for (int j = 0; j < 4; j++) {
            int col = (ch2 * 32 + j * 8 + 2 * tg) ^ sw;
            *(float2*)&g_h1[base + col] = make_float2(tfh(c2[mf][j][0]), tfh(c2[mf][j][1]));
            *(float2*)&g_h1[base + 8 * 128 + col] = make_float2(tfh(c2[mf][j][2]), tfh(c2[mf][j][3]));
        }
    }

    // s1/d1: partial dot per warp quarter, reduce via smem atomics, pre-scale log2e
    float sv[2][2], dv[2][2];
#pragma unroll
    for (int mf = 0; mf < 2; mf++)
#pragma unroll
        for (int rr = 0; rr < 2; rr++) { sv[mf][rr] = 0.0f; dv[mf][rr] = 0.0f; }
#pragma unroll
    for (int mf = 0; mf < 2; mf++)
#pragma unroll
        for (int j = 0; j < 4; j++)
#pragma unroll
            for (int e = 0; e < 4; e++) {
                int col = ch2 * 32 + j * 8 + 2 * tg + (e & 1);
                sv[mf][e >> 1] += c2[mf][j][e] * av[col];
                dv[mf][e >> 1] += c2[mf][j][e] * bv[col];
            }
#pragma unroll
    for (int mf = 0; mf < 2; mf++)
#pragma unroll
        for (int rr = 0; rr < 2; rr++) {
            sv[mf][rr] = qsum(sv[mf][rr]);
            dv[mf][rr] = qsum(dv[mf][rr]);
        }
    if (tg == 0) {
#pragma unroll
        for (int mf = 0; mf < 2; mf++)
#pragma unroll
            for (int rr = 0; rr < 2; rr++) {
                int r = st2 * 32 + mf * 16 + g + rr * 8;
                atomicAdd(&sdb[2 * r], sv[mf][rr]);
                atomicAdd(&sdb[2 * r + 1], dv[mf][rr]);
            }
    }
    __syncthreads();
    if (t < 64) {
        g_s1[b * NN + nb + t] = sdb[2 * t] * LOG2E;
        g_d1[b * NN + nb + t] = sdb[2 * t + 1] * LOG2E;
    }
}

// ------------------------- attn1: P-in-register mma, 1 head, D=128 ----------------------
#define A1_SMEM ((2*8192 + 512 + 1024) * 4)

__global__ __launch_bounds__(256, 2) void k_attn1_mma() {
    extern __shared__ float sm[];
    float* sH = sm;                      // 2 x 64x128
    float* sd = sH + 16384;              // 512
    unsigned long long* mkq = (unsigned long long*)(sd + 512);  // 64 x 8

    int b = blockIdx.y, nb = blockIdx.x * 64;
    int t = threadIdx.x, w = t >> 5, lane = t & 31, g = lane >> 2, tg = lane & 3;
    int st = w & 3, ch = w >> 2;

    const float* Hsrc = g_h1 + (size_t)b * NN * 128;
    issue_tile(sH, Hsrc, t);
    CP_COMMIT;

    for (int i = t; i < 512; i += 256) sd[i] = g_d1[b * NN + i];
    {
        const unsigned long long* gq =
            (const unsigned long long*)(g_mask + (size_t)(b * NN + nb) * NW);
        for (int i = t; i < 512; i += 256) mkq[i] = gq[i];
    }

    int r0 = st * 16 + g, r1 = r0 + 8;
    float s0v = g_s1[b * NN + nb + r0];
    float s1v = g_s1[b * NN + nb + r1];
    float S0 = 0.0f, S1 = 0.0f;
    float c[8][4];
#pragma unroll
    for (int j = 0; j < 8; j++)
#pragma unroll
        for (int e = 0; e < 4; e++) c[j][e] = 0.0f;

    for (int mt = 0; mt < 8; mt++) {
        CP_WAIT(0);
        __syncthreads();
        if (mt + 1 < 8) {
            issue_tile(sH + ((mt + 1) & 1) * 8192, Hsrc + (size_t)(mt + 1) * 8192, t);
            CP_COMMIT;
        }
        const float* Hb = sH + (mt & 1) * 8192;
        unsigned long long mw0 = mkq[r0 * 8 + mt];
        unsigned long long mw1 = mkq[r1 * 8 + mt];
        const float* dmt = sd + mt * 64;

#pragma unroll
        for (int kc = 0; kc < 8; kc++) {
            int c0 = kc * 8 + tg, c1 = c0 + 4;
            float d0 = dmt[c0], d1 = dmt[c1];
            float z0 = s0v + d0, z1 = s1v + d0;
            float z2 = s0v + d1, z3 = s1v + d1;
            float p0 = ((mw0 >> c0) & 1ull) ? ex2f(fmaxf(z0, 0.2f * z0)) : 0.0f;
            float p1 = ((mw1 >> c0) & 1ull) ? ex2f(fmaxf(z1, 0.2f * z1)) : 0.0f;
            float p2 = ((mw0 >> c1) & 1ull) ? ex2f(fmaxf(z2, 0.2f * z2)) : 0.0f;
            float p3 = ((mw1 >> c1) & 1ull) ? ex2f(fmaxf(z3, 0.2f * z3)) : 0.0f;
            S0 += p0 + p2;
            S1 += p1 + p3;
            unsigned a[4] = { f2tf(p0), f2tf(p1), f2tf(p2), f2tf(p3) };
            int sw0 = tg << 3;
#pragma unroll
            for (int j = 0; j < 8; j++) {
                int f = ch * 64 + j * 8 + g;
                unsigned bfr[2];
                bfr[0] = __float_as_uint(Hb[c0 * 128 + (f ^ sw0)]);
                bfr[1] = __float_as_uint(Hb[c1 * 128 + (f ^ sw0)]);
                mma_tf32(c[j], a, bfr);
            }
        }
    }
    S0 = qsum(S0); S1 = qsum(S1);
    float inv0 = 1.0f / S0, inv1 = 1.0f / S1;
    size_t base = ((size_t)b * NN + nb + r0) * 128;
#pragma unroll
    for (int j = 0; j < 8; j++) {
        int col = ch * 64 + j * 8 + 2 * tg;
        *(float2*)&g_m1[base + col] = make_float2(c[j][0] * inv0, c[j][1] * inv0);
        *(float2*)&g_m1[base + 8 * 128 + col] = make_float2(c[j][2] * inv1, c[j][3] * inv1);
    }
}

// ------------------------- fused tail (mma + aliased smem, occ 2) ------------------------
// region R = 16896 floats: ts (stride 260) aliased with ms (132) / us (132, +8448)
#define TAIL_SMEM ((16896 + 8192) * 4)

__device__ __forceinline__ void tail_mm(const float* __restrict__ Wg, const float* A,
                                        int astride, int K, float* ws, float c[2][4][4],
                                        int st, int ch, int g, int tg, int t) {
    int NS = K >> 6;
    for (int kt = 0; kt < NS; kt++) {
        issue_wtile(ws, Wg + (size_t)kt * 8192, t);
        CP_COMMIT;
        CP_WAIT(0);
        __syncthreads();
        for (int kc = 0; kc < 8; kc++) {
            unsigned a[2][4];
#pragma unroll
            for (int mf = 0; mf < 2; mf++) {
                const float* pr = A + (st * 32 + mf * 16 + g) * astride + kt * 64 + kc * 8;
                a[mf][0] = f2tf(pr[tg]);
                a[mf][1] = f2tf(pr[8 * astride + tg]);
                a[mf][2] = f2tf(pr[tg + 4]);
                a[mf][3] = f2tf(pr[8 * astride + tg + 4]);
            }
            int k0 = kc * 8 + tg, k1 = k0 + 4;
            int sw0 = tg << 3;
#pragma unroll
            for (int j = 0; j < 4; j++) {
                int f = ch * 32 + j * 8 + g;
                unsigned bfr[2];
                bfr[0] = f2tf(ws[k0 * 128 + (f ^ sw0)]);
                bfr[1] = f2tf(ws[k1 * 128 + (f ^ sw0)]);
                mma_tf32(c[0][j], a[0], bfr);
                mma_tf32(c[1][j], a[1], bfr);
            }
        }
        __syncthreads();   // all reads done before ws overwrite / A-region reuse
    }
}

__device__ __forceinline__ void frag_store(float* D, int dstride, float c[2][4][4],
                                           int st, int ch, int g, int tg) {
#pragma unroll
    for (int mf = 0; mf < 2; mf++) {
        int row = st * 32 + mf * 16 + g;
#pragma unroll
        for (int j = 0; j < 4; j++) {
            int col = ch * 32 + j * 8 + 2 * tg;
            *(float2*)&D[row * dstride + col] = make_float2(c[mf][j][0], c[mf][j][1]);
            *(float2*)&D[(row + 8) * dstride + col] = make_float2(c[mf][j][2], c[mf][j][3]);
        }
    }
}

__device__ __forceinline__ void frag_zero(float c[2][4][4]) {
#pragma unroll
    for (int mf = 0; mf < 2; mf++)
#pragma unroll
        for (int j = 0; j < 4; j++)
#pragma unroll
            for (int e = 0; e < 4; e++) c[mf][j][e] = 0.0f;
}

__global__ __launch_bounds__(256, 2) void k_tail(const float* __restrict__ x,
                       const float* __restrict__ ln1g, const float* __restrict__ ln1b,
                       const float* __restrict__ linW, const float* __restrict__ linb,
                       const float* __restrict__ meW0, const float* __restrict__ meb0,
                       const float* __restrict__ meW1, const float* __restrict__ meb1,
                       const float* __restrict__ ln2g, const float* __restrict__ ln2b,
                       const float* __restrict__ ohW, const float* __restrict__ ohb,
                       const float* __restrict__ ln3g, const float* __restrict__ ln3b,
                       float* __restrict__ out) {
    extern __shared__ float sm[];
    float* ts = sm;            // stride 260 (alive: concat/LN1 -> mm1 A)
    float* ms = sm;            // stride 132 (alias; alive mm1-out -> mm2 A, then frag buffers)
    float* us = sm + 8448;     // stride 132 (mm2-out -> mm3 A; ln2-out -> mm4 A)
    float* ws = sm + 16896;    // 64x128 weight tile

    int b = blockIdx.y, nb = blockIdx.x * 64;
    int t = threadIdx.x, cq = t & 3, nl = t >> 2;
    int w = t >> 5, lane = t & 31, g = lane >> 2, tg = lane & 3;
    int st = w & 1, ch = w >> 1;

    for (int i = t; i < 64 * 256; i += 256) {
        int r = i >> 8, j = i & 255;
        size_t row = (size_t)b * NN + nb + r;
        float v = (j < 128) ? x[row * 128 + j] : g_m1[row * 128 + (j - 128)];
        ts[r * 260 + j] = v;
    }
    __syncthreads();

    float sum = 0, sq = 0;
#pragma unroll 8
    for (int i = 0; i < 64; i++) {
        float v = ts[nl * 260 + cq * 64 + i];
        sum += v; sq += v * v;
    }
    sum = qsum(sum); sq = qsum(sq);
    float mu = sum * (1.0f / 256.0f);
    float rstd = rsqrtf(sq * (1.0f / 256.0f) - mu * mu + 1e-5f);
#pragma unroll 8
    for (int i = 0; i < 64; i++) {
        int j = cq * 64 + i;
        float v = ts[nl * 260 + j];
        ts[nl * 260 + j] = (v - mu) * rstd * ln1g[j] + ln1b[j];
    }

    float c[2][4][4];
    // mm1: m = LN1 @ linW   (A = ts; frag -> ms which aliases ts, safe after trailing sync)
    frag_zero(c);
    tail_mm(linW, ts, 260, 256, ws, c, st, ch, g, tg, t);
    frag_store(ms, 132, c, st, ch, g, tg);
    __syncthreads();
    float mreg[32];
#pragma unroll
    for (int d = 0; d < 32; d++) {
        int o = cq * 32 + d;
        mreg[d] = ms[nl * 132 + o] + linb[o];
        ms[nl * 132 + o] = mreg[d];
    }

    // mm2: u = gelu(m @ meW0 + meb0)
    frag_zero(c);
    tail_mm(meW0, ms, 132, 128, ws, c, st, ch, g, tg, t);
    frag_store(us, 132, c, st, ch, g, tg);
    __syncthreads();
#pragma unroll
    for (int d = 0; d < 32; d++) {
        int o = cq * 32 + d;
        us[nl * 132 + o] = gelu_exact(us[nl * 132 + o] + meb0[o]);
    }

    // mm3: enc = u @ meW1; r = m + enc + meb1; LN2 -> us
    frag_zero(c);
    tail_mm(meW1, us, 132, 128, ws, c, st, ch, g, tg, t);
    frag_store(ms, 132, c, st, ch, g, tg);
    __syncthreads();
    float a3[32];
    sum = 0; sq = 0;
#pragma unroll
    for (int d = 0; d < 32; d++) {
        int o = cq * 32 + d;
        a3[d] = ms[nl * 132 + o] + meb1[o] + mreg[d];
        sum += a3[d]; sq += a3[d] * a3[d];
    }
    sum = qsum(sum); sq = qsum(sq);
    mu = sum * (1.0f / 128.0f);
    rstd = rsqrtf(sq * (1.0f / 128.0f) - mu * mu + 1e-5f);
#pragma unroll
    for (int d = 0; d < 32; d++) {
        int o = cq * 32 + d;
        us[nl * 132 + o] = (a3[d] - mu) * rstd * ln2g[o] + ln2b[o];
    }

    // mm4: v = gelu(us @ ohW + ohb); LN3; out
    frag_zero(c);
    tail_mm(ohW, us, 132, 128, ws, c, st, ch, g, tg, t);
    frag_store(ms, 132, c, st, ch, g, tg);
    __syncthreads();
    float a4[32];
    sum = 0; sq = 0;
#pragma unroll
    for (int d = 0; d < 32; d++) {
        int o = cq * 32 + d;
        float v = gelu_exact(ms[nl * 132 + o] + ohb[o]);
        a4[d] = v;
        sum += v; sq += v * v;
    }
    sum = qsum(sum); sq = qsum(sq);
    mu = sum * (1.0f / 128.0f);
    rstd = rsqrtf(sq * (1.0f / 128.0f) - mu * mu + 1e-5f);

    float* op = out + ((size_t)b * NN + nb + nl) * 128 + cq * 32;
#pragma unroll
    for (int d4 = 0; d4 < 8; d4++) {
        float r0 = (a4[4 * d4 + 0] - mu) * rstd * ln3g[cq * 32 + 4 * d4 + 0] + ln3b[cq * 32 + 4 * d4 + 0];
        float r1 = (a4[4 * d4 + 1] - mu) * rstd * ln3g[cq * 32 + 4 * d4 + 1] + ln3b[cq * 32 + 4 * d4 + 1];
        float r2 = (a4[4 * d4 + 2] - mu) * rstd * ln3g[cq * 32 + 4 * d4 + 2] + ln3b[cq * 32 + 4 * d4 + 2];
        float r3 = (a4[4 * d4 + 3] - mu) * rstd * ln3g[cq * 32 + 4 * d4 + 3] + ln3b[cq * 32 + 4 * d4 + 3];
        ((float4*)op)[d4] = make_float4(r0, r1, r2, r3);
    }
}

// ------------------------- launch -------------------------
extern "C" void kernel_launch(void* const* d_in, const int* in_sizes, int n_in,
                              void* d_out, int out_size) {
    const float* x    = (const float*)d_in[0];
    const int*   grp  = (const int*)  d_in[1];
    const float* W0   = (const float*)d_in[2];
    const float* as0  = (const float*)d_in[3];
    const float* ad0  = (const float*)d_in[4];
    const float* W1   = (const float*)d_in[5];
    const float* as1  = (const float*)d_in[6];
    const float* ad1  = (const float*)d_in[7];
    const float* ln1g = (const float*)d_in[8];
    const float* ln1b = (const float*)d_in[9];
    const float* linW = (const float*)d_in[10];
    const float* linb = (const float*)d_in[11];
    const float* meW0 = (const float*)d_in[12];
    const float* meb0 = (const float*)d_in[13];
    const float* meW1 = (const float*)d_in[14];
    const float* meb1 = (const float*)d_in[15];
    const float* ln2g = (const float*)d_in[16];
    const float* ln2b = (const float*)d_in[17];
    const float* ohW  = (const float*)d_in[18];
    const float* ohb  = (const float*)d_in[19];
    const float* ln3g = (const float*)d_in[20];
    const float* ln3b = (const float*)d_in[21];
    float* out = (float*)d_out;

    cudaFuncSetAttribute(k_proj0, cudaFuncAttributeMaxDynamicSharedMemorySize, P0_SMEM);
    cudaFuncSetAttribute(k_attn0, cudaFuncAttributeMaxDynamicSharedMemorySize, A0_SMEM);
    cudaFuncSetAttribute(k_attn1_mma, cudaFuncAttributeMaxDynamicSharedMemorySize, A1_SMEM);
    cudaFuncSetAttribute(k_tail, cudaFuncAttributeMaxDynamicSharedMemorySize, TAIL_SMEM);

    dim3 grid(NN / 64, BB);
    k_proj0<<<grid, 256, P0_SMEM>>>(x, W0, as0, ad0);
    k_attn0<<<grid, 256, A0_SMEM>>>(grp, W1, as1, ad1);
    k_attn1_mma<<<grid, 256, A1_SMEM>>>();
    k_tail<<<grid, 256, TAIL_SMEM>>>(x, ln1g, ln1b, linW, linb,
                                     meW0, meb0, meW1, meb1,
                                     ln2g, ln2b, ohW, ohb,
                                     ln3g, ln3b, out);
}

// round 7
// speedup vs baseline: 7.1718x; 1.0556x over previous
#include <cuda_runtime.h>
#include <math.h>

#define BB 32
#define NN 512
#define NH 4
#define NW 16
#define LOG2E 1.4426950408889634f

// ------------------------- scratch (device globals; no allocation) -------------------------
// h0/h1 live as tf32-bit, XOR-swizzled 64x128 tiles: elem (n, c) at
//   (b*NN + n)*128 + (c ^ ((n&3)<<3))
__device__ __align__(16) float    g_h0[(size_t)BB*NN*128];
__device__ float    g_s0[BB*NH*NN];   // pre-scaled by log2e
__device__ float    g_d0[BB*NH*NN];
__device__ __align__(16) float    g_h1[(size_t)BB*NN*128];
__device__ float    g_s1[BB*NN];      // pre-scaled by log2e
__device__ float    g_d1[BB*NN];
__device__ __align__(16) unsigned g_mask[BB*NN*NW];
// pre-converted (tf32 bits) + pre-swizzled weight tiles (64x128 each):
// tiles 0-1: W0 | 2-3: W1 | 4-7: linW | 8-9: meW0 | 10-11: meW1 | 12-13: ohW
__device__ __align__(16) float    g_wtf[14 * 8192];

// ------------------------- helpers -------------------------
__device__ __forceinline__ float qsum(float v) {
    v += __shfl_xor_sync(0xffffffffu, v, 1);
    v += __shfl_xor_sync(0xffffffffu, v, 2);
    return v;
}
__device__ __forceinline__ float gelu_exact(float v) {
    return 0.5f * v * (1.0f + erff(v * 0.70710678118654752f));
}
__device__ __forceinline__ unsigned f2tf(float f) {
    unsigned u; asm("cvt.rna.tf32.f32 %0, %1;" : "=r"(u) : "f"(f)); return u;
}
__device__ __forceinline__ float tfh(float f) { return __uint_as_float(f2tf(f)); }
__device__ __forceinline__ float ex2f(float x) {
    float y; asm("ex2.approx.f32 %0, %1;" : "=f"(y) : "f"(x)); return y;
}
__device__ __forceinline__ void mma_tf32(float c[4], const unsigned a[4], const unsigned b[2]) {
    asm volatile("mma.sync.aligned.m16n8k8.row.col.f32.tf32.tf32.f32 "
                 "{%0,%1,%2,%3}, {%4,%5,%6,%7}, {%8,%9}, {%0,%1,%2,%3};"
                 : "+f"(c[0]), "+f"(c[1]), "+f"(c[2]), "+f"(c[3])
                 : "r"(a[0]), "r"(a[1]), "r"(a[2]), "r"(a[3]), "r"(b[0]), "r"(b[1]));
}
__device__ __forceinline__ unsigned sptr(const void* p) {
    return (unsigned)__cvta_generic_to_shared(p);
}
__device__ __forceinline__ void cpa16(unsigned s, const void* g) {
    asm volatile("cp.async.cg.shared.global [%0], [%1], 16;" :: "r"(s), "l"(g));
}
#define CP_COMMIT asm volatile("cp.async.commit_group;")
#define CP_WAIT(n) asm volatile("cp.async.wait_group %0;" :: "n"(n))

// raw 16B-chunk copy of a 64x128-float tile (layout preserved)
__device__ __forceinline__ void issue_tile(float* dst, const float* __restrict__ src, int t) {
    for (int i = t; i < 2048; i += 256) cpa16(sptr(dst + i * 4), src + i * 4);
}
// raw copy of a 32x128-float half tile
__device__ __forceinline__ void issue_half(float* dst, const float* __restrict__ src, int t) {
    for (int i = t; i < 1024; i += 256) cpa16(sptr(dst + i * 4), src + i * 4);
}
// 64x128 tile with XOR swizzle applied on 16B granularity (raw fp32)
__device__ __forceinline__ void issue_wtile(float* dst, const float* __restrict__ src, int t) {
    for (int i = t; i < 2048; i += 256) {
        int r = i >> 5, c4 = (i & 31) * 4;
        cpa16(sptr(dst + r * 128 + (c4 ^ ((r & 3) << 3))), src + (size_t)r * 128 + c4);
    }
}

// ------------------------- weight prep: fp32 -> tf32 bits, swizzled tiles ----------------
__global__ void k_wprep(const float* __restrict__ W0, const float* __restrict__ W1,
                        const float* __restrict__ linW, const float* __restrict__ meW0,
                        const float* __restrict__ meW1, const float* __restrict__ ohW) {
    int c4i = blockIdx.x * 256 + threadIdx.x;        // float4 index, 28672 total
    int fl = c4i * 4;
    int T = fl >> 13;
    int off = fl & 8191;
    int r = off >> 7, cc = off & 127;
    const float* src; int rowbase;
    if (T < 2)       { src = W0;   rowbase = T * 64; }
    else if (T < 4)  { src = W1;   rowbase = (T - 2) * 64; }
    else if (T < 8)  { src = linW; rowbase = (T - 4) * 64; }
    else if (T < 10) { src = meW0; rowbase = (T - 8) * 64; }
    else if (T < 12) { src = meW1; rowbase = (T - 10) * 64; }
    else             { src = ohW;  rowbase = (T - 12) * 64; }
    float4 v = *(const float4*)&src[(size_t)(rowbase + r) * 128 + cc];
    float4 o; o.x = tfh(v.x); o.y = tfh(v.y); o.z = tfh(v.z); o.w = tfh(v.w);
    *(float4*)&g_wtf[T * 8192 + r * 128 + (cc ^ ((r & 3) << 3))] = o;
}

// ------------------------- proj0: h0 = X@W0 (64x128x128 per CTA) + s0/d0 -------------------
#define P0_SMEM ((8192 + 16384) * 4)

__global__ __launch_bounds__(256, 2) void k_proj0(const float* __restrict__ x,
                                                  const float* __restrict__ av,
                                                  const float* __restrict__ bv) {
    extern __shared__ float sm[];
    float* xs = sm;            // 64x128 raw fp32 swizzled A
    float* ws = xs + 8192;     // 2 x 64x128 tf32 swizzled W0

    int b = blockIdx.y, nb = blockIdx.x * 64;
    int t = threadIdx.x, w = t >> 5, lane = t & 31, g = lane >> 2, tg = lane & 3;
    int st = w & 1, ch = w >> 1;

    issue_wtile(xs, x + ((size_t)b * NN + nb) * 128, t);
    issue_tile(ws, g_wtf, t);
    CP_COMMIT;
    issue_tile(ws + 8192, g_wtf + 8192, t);
    CP_COMMIT;

    float c[2][4][4];
#pragma unroll
    for (int mf = 0; mf < 2; mf++)
#pragma unroll
        for (int j = 0; j < 4; j++)
#pragma unroll
            for (int e = 0; e < 4; e++) c[mf][j][e] = 0.0f;

#pragma unroll
    for (int kt = 0; kt < 2; kt++) {
        if (kt == 0) { CP_WAIT(1); } else { CP_WAIT(0); }
        __syncthreads();
        const float* wsb = ws + kt * 8192;
        for (int kc = 0; kc < 8; kc++) {
            unsigned a[2][4];
#pragma unroll
            for (int mf = 0; mf < 2; mf++) {
                int r = st * 32 + mf * 16 + g;
                int sw = (r & 3) << 3;
                int kb = kt * 64 + kc * 8;
                a[mf][0] = f2tf(xs[r * 128 + ((kb + tg) ^ sw)]);
                a[mf][1] = f2tf(xs[(r + 8) * 128 + ((kb + tg) ^ sw)]);
                a[mf][2] = f2tf(xs[r * 128 + ((kb + tg + 4) ^ sw)]);
                a[mf][3] = f2tf(xs[(r + 8) * 128 + ((kb + tg + 4) ^ sw)]);
            }
            int k0 = kc * 8 + tg, k1 = k0 + 4;
            int sw0 = tg << 3;
#pragma unroll
            for (int j = 0; j < 4; j++) {
                int f = ch * 32 + j * 8 + g;
                unsigned bfr[2];
                bfr[0] = __float_as_uint(wsb[k0 * 128 + (f ^ sw0)]);
                bfr[1] = __float_as_uint(wsb[k1 * 128 + (f ^ sw0)]);
                mma_tf32(c[0][j], a[0], bfr);
                mma_tf32(c[1][j], a[1], bfr);
            }
        }
    }

    // h0 write (tf32 swizzled)
#pragma unroll
    for (int mf = 0; mf < 2; mf++) {
        int row = st * 32 + mf * 16 + g;
        size_t base = ((size_t)b * NN + nb + row) * 128;
        int sw = (row & 3) << 3;
#pragma unroll
        for (int j = 0; j < 4; j++) {
            int col = (ch * 32 + j * 8 + 2 * tg) ^ sw;
            *(float2*)&g_h0[base + col] = make_float2(tfh(c[mf][j][0]), tfh(c[mf][j][1]));
            *(float2*)&g_h0[base + 8 * 128 + col] = make_float2(tfh(c[mf][j][2]), tfh(c[mf][j][3]));
        }
    }

    // s0/d0 (head == ch), pre-scaled by log2e
    float sv[2][2], dv[2][2];
#pragma unroll
    for (int mf = 0; mf < 2; mf++)
#pragma unroll
        for (int rr = 0; rr < 2; rr++) { sv[mf][rr] = 0.0f; dv[mf][rr] = 0.0f; }
#pragma unroll
    for (int mf = 0; mf < 2; mf++)
#pragma unroll
        for (int j = 0; j < 4; j++)
#pragma unroll
            for (int e = 0; e < 4; e++) {
                int col = ch * 32 + j * 8 + 2 * tg + (e & 1);
                sv[mf][e >> 1] += c[mf][j][e] * av[col];
                dv[mf][e >> 1] += c[mf][j][e] * bv[col];
            }
#pragma unroll
    for (int mf = 0; mf < 2; mf++)
#pragma unroll
        for (int rr = 0; rr < 2; rr++) {
            sv[mf][rr] = qsum(sv[mf][rr]);
            dv[mf][rr] = qsum(dv[mf][rr]);
        }
    if (tg == 0) {
#pragma unroll
        for (int mf = 0; mf < 2; mf++)
#pragma unroll
            for (int rr = 0; rr < 2; rr++) {
                int r = st * 32 + mf * 16 + g + rr * 8;
                g_s0[(b * NH + ch) * NN + nb + r] = sv[mf][rr] * LOG2E;
                g_d0[(b * NH + ch) * NN + nb + r] = dv[mf][rr] * LOG2E;
            }
    }
}

// ------------------------- attn0 fused: mask-gen + GAT0 softmax-agg + ELU + proj1 ----------
#define A0_SMEM ((16384 + 2048 + 1024 + 8192 + 128) * 4)

__global__ __launch_bounds__(256, 2) void k_attn0(const int* __restrict__ graph,
                                                  const float* __restrict__ av,
                                                  const float* __restrict__ bv) {
    extern __shared__ float sm[];
    float* sH = sm;                                // 2 x 64x128 (H tiles, later W1 tiles)
    float* sd = sH + 16384;                        // 4 x 512 d0
    unsigned* mk32 = (unsigned*)(sd + 2048);       // 1024 mask words
    float* xm = (float*)(mk32 + 1024);             // 64x128 m0 tile (tf32 swizzled)
    float* sdb = xm + 8192;                        // 128 (s1/d1 accum)

    int b = blockIdx.y, nb = blockIdx.x * 64;
    int t = threadIdx.x, w = t >> 5, lane = t & 31, g = lane >> 2, tg = lane & 3;
    int h = w >> 1, s0r = (w & 1) * 16;

    const float* Hsrc = g_h0 + (size_t)b * NN * 128;
    issue_tile(sH, Hsrc, t);
    CP_COMMIT;

    if (t < 128) sdb[t] = 0.0f;

    // mask generation for rows nb..nb+63 (ballot over graph)
    for (int wi = w; wi < 1024; wi += 8) {
        int row = wi >> 4, mq = wi & 15;
        int m = mq * 32 + lane, gn = nb + row;
        bool pred = (graph[((size_t)b * NN + gn) * NN + m] > 0) || (gn == m);
        unsigned bits = __ballot_sync(0xffffffffu, pred);
        if (lane == 0) mk32[wi] = bits;
    }
    for (int i = t; i < 2048; i += 256) sd[i] = g_d0[b * NH * NN + i];
    __syncthreads();
    // publish masks for attn1
    ((uint4*)(g_mask + (size_t)(b * NN + nb) * NW))[t] = ((uint4*)mk32)[t];

    const unsigned long long* mkq = (const unsigned long long*)mk32;

    int rows[4] = { s0r + g, s0r + g + 8, s0r + 32 + g, s0r + 40 + g };
    float srow[4], S[4];
#pragma unroll
    for (int rr = 0; rr < 4; rr++) {
        srow[rr] = g_s0[(b * NH + h) * NN + nb + rows[rr]];
        S[rr] = 0.0f;
    }
    float c[2][4][4];
#pragma unroll
    for (int sp = 0; sp < 2; sp++)
#pragma unroll
        for (int j = 0; j < 4; j++)
#pragma unroll
            for (int e = 0; e < 4; e++) c[sp][j][e] = 0.0f;

    const float* dh = sd + h * 512;

    for (int mt = 0; mt < 8; mt++) {
        CP_WAIT(0);
        __syncthreads();
        if (mt + 1 < 8) {
            issue_tile(sH + ((mt + 1) & 1) * 8192, Hsrc + (size_t)(mt + 1) * 8192, t);
            CP_COMMIT;
        } else {
            issue_tile(sH, g_wtf + 2 * 8192, t);   // W1 tile0 into sH[0] (free during mt=7)
            CP_COMMIT;
        }
        const float* Hb = sH + (mt & 1) * 8192;
        unsigned long long mw[4];
#pragma unroll
        for (int rr = 0; rr < 4; rr++) mw[rr] = mkq[rows[rr] * 8 + mt];
        const float* dmt = dh + mt * 64;

#pragma unroll
        for (int kc = 0; kc < 8; kc++) {
            int c0 = kc * 8 + tg, c1 = c0 + 4;
            float d0 = dmt[c0], d1 = dmt[c1];
            int sw0 = tg << 3;
            unsigned bfr[4][2];
#pragma unroll
            for (int j = 0; j < 4; j++) {
                int f = h * 32 + j * 8 + g;
                bfr[j][0] = __float_as_uint(Hb[c0 * 128 + (f ^ sw0)]);
                bfr[j][1] = __float_as_uint(Hb[c1 * 128 + (f ^ sw0)]);
            }
#pragma unroll
            for (int sp = 0; sp < 2; sp++) {
                int r0 = sp * 2, r1 = sp * 2 + 1;
                float z0 = srow[r0] + d0, z1 = srow[r1] + d0;
                float z2 = srow[r0] + d1, z3 = srow[r1] + d1;
                float p0 = ((mw[r0] >> c0) & 1ull) ? ex2f(fmaxf(z0, 0.2f * z0)) : 0.0f;
                float p1 = ((mw[r1] >> c0) & 1ull) ? ex2f(fmaxf(z1, 0.2f * z1)) : 0.0f;
                float p2 = ((mw[r0] >> c1) & 1ull) ? ex2f(fmaxf(z2, 0.2f * z2)) : 0.0f;
                float p3 = ((mw[r1] >> c1) & 1ull) ? ex2f(fmaxf(z3, 0.2f * z3)) : 0.0f;
                S[r0] += p0 + p2;
                S[r1] += p1 + p3;
                unsigned a[4] = { f2tf(p0), f2tf(p1), f2tf(p2), f2tf(p3) };
#pragma unroll
                for (int j = 0; j < 4; j++) mma_tf32(c[sp][j], a, bfr[j]);
            }
        }
    }
#pragma unroll
    for (int rr = 0; rr < 4; rr++) S[rr] = qsum(S[rr]);

    // m0 epilogue: /S, elu, tf32, into smem xm (swizzled)
#pragma unroll
    for (int sp = 0; sp < 2; sp++) {
        float inv0 = 1.0f / S[sp * 2], inv1 = 1.0f / S[sp * 2 + 1];
        int r0 = s0r + sp * 32 + g;
        int sw = (r0 & 3) << 3;
#pragma unroll
        for (int j = 0; j < 4; j++) {
            int col = (h * 32 + j * 8 + 2 * tg) ^ sw;
            float v0 = c[sp][j][0] * inv0, v1 = c[sp][j][1] * inv0;
            float v2 = c[sp][j][2] * inv1, v3 = c[sp][j][3] * inv1;
            v0 = v0 > 0.0f ? v0 : expm1f(v0);
            v1 = v1 > 0.0f ? v1 : expm1f(v1);
            v2 = v2 > 0.0f ? v2 : expm1f(v2);
            v3 = v3 > 0.0f ? v3 : expm1f(v3);
            *(float2*)&xm[r0 * 128 + col] = make_float2(tfh(v0), tfh(v1));
            *(float2*)&xm[(r0 + 8) * 128 + col] = make_float2(tfh(v2), tfh(v3));
        }
    }
    __syncthreads();                      // xm complete; sH[1] free
    issue_tile(sH + 8192, g_wtf + 3 * 8192, t);
    CP_COMMIT;

    // ---- fused proj1: h1 = m0 @ W1, 64x128x128 ----
    int st2 = w & 1, ch2 = w >> 1;
    float c2[2][4][4];
#pragma unroll
    for (int mf = 0; mf < 2; mf++)
#pragma unroll
        for (int j = 0; j < 4; j++)
#pragma unroll
            for (int e = 0; e < 4; e++) c2[mf][j][e] = 0.0f;

#pragma unroll
    for (int kt = 0; kt < 2; kt++) {
        if (kt == 0) { CP_WAIT(1); } else { CP_WAIT(0); }
        __syncthreads();
        const float* wsb = sH + kt * 8192;
        for (int kc = 0; kc < 8; kc++) {
            unsigned a[2][4];
#pragma unroll
            for (int mf = 0; mf < 2; mf++) {
                int r = st2 * 32 + mf * 16 + g;
                int sw = (r & 3) << 3;
                int kb = kt * 64 + kc * 8;
                a[mf][0] = __float_as_uint(xm[r * 128 + ((kb + tg) ^ sw)]);
                a[mf][1] = __float_as_uint(xm[(r + 8) * 128 + ((kb + tg) ^ sw)]);
                a[mf][2] = __float_as_uint(xm[r * 128 + ((kb + tg + 4) ^ sw)]);
                a[mf][3] = __float_as_uint(xm[(r + 8) * 128 + ((kb + tg + 4) ^ sw)]);
            }
            int k0 = kc * 8 + tg, k1 = k0 + 4;
            int sw0 = tg << 3;
#pragma unroll
            for (int j = 0; j < 4; j++) {
                int f = ch2 * 32 + j * 8 + g;
                unsigned bfr[2];
                bfr[0] = __float_as_uint(wsb[k0 * 128 + (f ^ sw0)]);
                bfr[1] = __float_as_uint(wsb[k1 * 128 + (f ^ sw0)]);
                mma_tf32(c2[0][j], a[0], bfr);
                mma_tf32(c2[1][j], a[1], bfr);
            }
        }
    }

    // h1 write (tf32 swizzled)
#pragma unroll
    for (int mf = 0; mf < 2; mf++) {
        int row = st2 * 32 + mf * 16 + g;
        size_t base = ((size_t)b * NN + nb + row) * 128;
        int sw = (row & 3) << 3;
#pragma unroll
        for (int j = 0; j < 4; j++) {
            int col = (ch2 * 32 + j * 8 + 2 * tg) ^ sw;
            *(float2*)&g_h1[base + col] = make_float2(tfh(c2[mf][j][0]), tfh(c2[mf][j][1]));
            *(float2*)&g_h1[base + 8 * 128 + col] = make_float2(tfh(c2[mf][j][2]), tfh(c2[mf][j][3]));
        }
    }

    // s1/d1 epilogue
    float sv[2][2], dv[2][2];
#pragma unroll
    for (int mf = 0; mf < 2; mf++)
#pragma unroll
        for (int rr = 0; rr < 2; rr++) { sv[mf][rr] = 0.0f; dv[mf][rr] = 0.0f; }
#pragma unroll
    for (int mf = 0; mf < 2; mf++)
#pragma unroll
        for (int j = 0; j < 4; j++)
#pragma unroll
            for (int e = 0; e < 4; e++) {
                int col = ch2 * 32 + j * 8 + 2 * tg + (e & 1);
                sv[mf][e >> 1] += c2[mf][j][e] * av[col];
                dv[mf][e >> 1] += c2[mf][j][e] * bv[col];
            }
#pragma unroll
    for (int mf = 0; mf < 2; mf++)
#pragma unroll
        for (int rr = 0; rr < 2; rr++) {
            sv[mf][rr] = qsum(sv[mf][rr]);
            dv[mf][rr] = qsum(dv[mf][rr]);
        }
    if (tg == 0) {
#pragma unroll
        for (int mf = 0; mf < 2; mf++)
#pragma unroll
            for (int rr = 0; rr < 2; rr++) {
                int r = st2 * 32 + mf * 16 + g + rr * 8;
                atomicAdd(&sdb[2 * r], sv[mf][rr]);
                atomicAdd(&sdb[2 * r + 1], dv[mf][rr]);
            }
    }
    __syncthreads();
    if (t < 64) {
        g_s1[b * NN + nb + t] = sdb[2 * t] * LOG2E;
        g_d1[b * NN + nb + t] = sdb[2 * t + 1] * LOG2E;
    }
}

// ------------------------- fused attn1 + tail -------------------------
// smem floats: [0,16384) sH 2buf | [16384,16896) sd | [16896,17920) mk | [17920,26112) ws 2x4096
// after attn phase: ts (stride 260, 16640) aliases sH+sd; ms/us alias ts.
#define A1T_SMEM ((17920 + 8192) * 4)

__device__ __forceinline__ void tail_mm(const float* __restrict__ Wt, const float* A,
                                        int astride, int K, float* ws, float c[2][4][4],
                                        int st, int ch, int g, int tg, int t) {
    int NC = K >> 5;
    issue_half(ws, Wt, t);
    CP_COMMIT;
    for (int kt = 0; kt < NC; kt++) {
        if (kt + 1 < NC) {
            issue_half(ws + ((kt + 1) & 1) * 4096, Wt + (size_t)(kt + 1) * 4096, t);
            CP_COMMIT;
            CP_WAIT(1);
        } else {
            CP_WAIT(0);
        }
        __syncthreads();
        const float* wsb = ws + (kt & 1) * 4096;
        for (int kc = 0; kc < 4; kc++) {
            unsigned a[2][4];
#pragma unroll
            for (int mf = 0; mf < 2; mf++) {
                const float* pr = A + (st * 32 + mf * 16 + g) * astride + kt * 32 + kc * 8;
                a[mf][0] = f2tf(pr[tg]);
                a[mf][1] = f2tf(pr[8 * astride + tg]);
                a[mf][2] = f2tf(pr[tg + 4]);
                a[mf][3] = f2tf(pr[8 * astride + tg + 4]);
            }
            int k0 = kc * 8 + tg, k1 = k0 + 4;
            int sw0 = tg << 3;
#pragma unroll
            for (int j = 0; j < 4; j++) {
                int f = ch * 32 + j * 8 + g;
                unsigned bfr[2];
                bfr[0] = __float_as_uint(wsb[k0 * 128 + (f ^ sw0)]);
                bfr[1] = __float_as_uint(wsb[k1 * 128 + (f ^ sw0)]);
                mma_tf32(c[0][j], a[0], bfr);
                mma_tf32(c[1][j], a[1], bfr);
            }
        }
        __syncthreads();
    }
}

__device__ __forceinline__ void frag_store(float* D, int dstride, float c[2][4][4],
                                           int st, int ch, int g, int tg) {
#pragma unroll
    for (int mf = 0; mf < 2; mf++) {
        int row = st * 32 + mf * 16 + g;
#pragma unroll
        for (int j = 0; j < 4; j++) {
            int col = ch * 32 + j * 8 + 2 * tg;
            *(float2*)&D[row * dstride + col] = make_float2(c[mf][j][0], c[mf][j][1]);
            *(float2*)&D[(row + 8) * dstride + col] = make_float2(c[mf][j][2], c[mf][j][3]);
        }
    }
}

__device__ __forceinline__ void frag_zero(float c[2][4][4]) {
#pragma unroll
    for (int mf = 0; mf < 2; mf++)
#pragma unroll
        for (int j = 0; j < 4; j++)
#pragma unroll
            for (int e = 0; e < 4; e++) c[mf][j][e] = 0.0f;
}

__global__ __launch_bounds__(256, 2) void k_a1tail(const float* __restrict__ x,
                       const float* __restrict__ ln1g, const float* __restrict__ ln1b,
                       const float* __restrict__ linb,
                       const float* __restrict__ meb0, const float* __restrict__ meb1,
                       const float* __restrict__ ln2g, const float* __restrict__ ln2b,
                       const float* __restrict__ ohb,
                       const float* __restrict__ ln3g, const float* __restrict__ ln3b,
                       float* __restrict__ out) {
    extern __shared__ float sm[];
    float* sH = sm;                      // 2 x 64x128
    float* sd = sH + 16384;              // 512
    unsigned long long* mkq = (unsigned long long*)(sd + 512);  // 64 x 8
    float* ts = sm;                      // stride 260 (aliases sH/sd after attn)
    float* ms = sm;                      // stride 132
    float* us = sm + 8448;               // stride 132
    float* ws = sm + 17920;              // 2 x 32x128 weight chunks

    int b = blockIdx.y, nb = blockIdx.x * 64;
    int t = threadIdx.x, cq = t & 3, nl = t >> 2;
    int w = t >> 5, lane = t & 31, g = lane >> 2, tg = lane & 3;

    // ======== attn1 phase ========
    {
        int st = w & 3, ch = w >> 2;
        const float* Hsrc = g_h1 + (size_t)b * NN * 128;
        issue_tile(sH, Hsrc, t);
        CP_COMMIT;

        for (int i = t; i < 512; i += 256) sd[i] = g_d1[b * NN + i];
        {
            const unsigned long long* gq =
                (const unsigned long long*)(g_mask + (size_t)(b * NN + nb) * NW);
            for (int i = t; i < 512; i += 256) mkq[i] = gq[i];
        }

        int r0 = st * 16 + g, r1 = r0 + 8;
        float s0v = g_s1[b * NN + nb + r0];
        float s1v = g_s1[b * NN + nb + r1];
        float S0 = 0.0f, S1 = 0.0f;
        float c[8][4];
#pragma unroll
        for (int j = 0; j < 8; j++)
#pragma unroll
            for (int e = 0; e < 4; e++) c[j][e] = 0.0f;

        for (int mt = 0; mt < 8; mt++) {
            CP_WAIT(0);
            __syncthreads();
            if (mt + 1 < 8) {
                issue_tile(sH + ((mt + 1) & 1) * 8192, Hsrc + (size_t)(mt + 1) * 8192, t);
                CP_COMMIT;
            }
            const float* Hb = sH + (mt & 1) * 8192;
            unsigned long long mw0 = mkq[r0 * 8 + mt];
            unsigned long long mw1 = mkq[r1 * 8 + mt];
            const float* dmt = sd + mt * 64;

#pragma unroll
            for (int kc = 0; kc < 8; kc++) {
                int c0 = kc * 8 + tg, c1 = c0 + 4;
                float d0 = dmt[c0], d1 = dmt[c1];
                float z0 = s0v + d0, z1 = s1v + d0;
                float z2 = s0v + d1, z3 = s1v + d1;
                float p0 = ((mw0 >> c0) & 1ull) ? ex2f(fmaxf(z0, 0.2f * z0)) : 0.0f;
                float p1 = ((mw1 >> c0) & 1ull) ? ex2f(fmaxf(z1, 0.2f * z1)) : 0.0f;
                float p2 = ((mw0 >> c1) & 1ull) ? ex2f(fmaxf(z2, 0.2f * z2)) : 0.0f;
                float p3 = ((mw1 >> c1) & 1ull) ? ex2f(fmaxf(z3, 0.2f * z3)) : 0.0f;
                S0 += p0 + p2;
                S1 += p1 + p3;
                unsigned a[4] = { f2tf(p0), f2tf(p1), f2tf(p2), f2tf(p3) };
                int sw0 = tg << 3;
#pragma unroll
                for (int j = 0; j < 8; j++) {
                    int f = ch * 64 + j * 8 + g;
                    unsigned bfr[2];
                    bfr[0] = __float_as_uint(Hb[c0 * 128 + (f ^ sw0)]);
                    bfr[1] = __float_as_uint(Hb[c1 * 128 + (f ^ sw0)]);
                    mma_tf32(c[j], a, bfr);
                }
            }
        }
        S0 = qsum(S0); S1 = qsum(S1);
        float inv0 = 1.0f / S0, inv1 = 1.0f / S1;

        __syncthreads();   // everyone done reading sH/sd; ts overwrite is safe

        // x -> ts cols 0..127 (async), m1 -> ts cols 128..255 (from registers)
        for (int i = t; i < 2048; i += 256) {
            int r = i >> 5, c4 = (i & 31) * 4;
            cpa16(sptr(ts + r * 260 + c4), x + ((size_t)(b * NN + nb) + r) * 128 + c4);
        }
        CP_COMMIT;
#pragma unroll
        for (int j = 0; j < 8; j++) {
            int col = 128 + ch * 64 + j * 8 + 2 * tg;
            *(float2*)&ts[r0 * 260 + col] = make_float2(c[j][0] * inv0, c[j][1] * inv0);
            *(float2*)&ts[(r0 + 8) * 260 + col] = make_float2(c[j][2] * inv1, c[j][3] * inv1);
        }
        CP_WAIT(0);
        __syncthreads();
    }

    // ======== tail phase ========
    int st = w & 1, ch = w >> 1;

    // LN1 over 256
    float sum = 0, sq = 0;
#pragma unroll 8
    for (int i = 0; i < 64; i++) {
        float v = ts[nl * 260 + cq * 64 + i];
        sum += v; sq += v * v;
    }
    sum = qsum(sum); sq = qsum(sq);
    float mu = sum * (1.0f / 256.0f);
    float rstd = rsqrtf(sq * (1.0f / 256.0f) - mu * mu + 1e-5f);
#pragma unroll 8
    for (int i = 0; i < 64; i++) {
        int j = cq * 64 + i;
        float v = ts[nl * 260 + j];
        ts[nl * 260 + j] = (v - mu) * rstd * ln1g[j] + ln1b[j];
    }

    float c[2][4][4];
    // mm1: m = LN1 @ linW
    frag_zero(c);
    tail_mm(g_wtf + 4 * 8192, ts, 260, 256, ws, c, st, ch, g, tg, t);
    frag_store(ms, 132, c, st, ch, g, tg);
    __syncthreads();
    float mreg[32];
#pragma unroll
    for (int d = 0; d < 32; d++) {
        int o = cq * 32 + d;
        mreg[d] = ms[nl * 132 + o] + linb[o];
        ms[nl * 132 + o] = mreg[d];
    }

    // mm2: u = gelu(m @ meW0 + meb0)
    frag_zero(c);
    tail_mm(g_wtf + 8 * 8192, ms, 132, 128, ws, c, st, ch, g, tg, t);
    frag_store(us, 132, c, st, ch, g, tg);
    __syncthreads();
#pragma unroll
    for (int d = 0; d < 32; d++) {
        int o = cq * 32 + d;
        us[nl * 132 + o] = gelu_exact(us[nl * 132 + o] + meb0[o]);
    }

    // mm3: enc = u @ meW1; r = m + enc + meb1; LN2 -> us
    frag_zero(c);
    tail_mm(g_wtf + 10 * 8192, us, 132, 128, ws, c, st, ch, g, tg, t);
    frag_store(ms, 132, c, st, ch, g, tg);
    __syncthreads();
    float a3[32];
    sum = 0; sq = 0;
#pragma unroll
    for (int d = 0; d < 32; d++) {
        int o = cq * 32 + d;
        a3[d] = ms[nl * 132 + o] + meb1[o] + mreg[d];
        sum += a3[d]; sq += a3[d] * a3[d];
    }
    sum = qsum(sum); sq = qsum(sq);
    mu = sum * (1.0f / 128.0f);
    rstd = rsqrtf(sq * (1.0f / 128.0f) - mu * mu + 1e-5f);
#pragma unroll
    for (int d = 0; d < 32; d++) {
        int o = cq * 32 + d;
        us[nl * 132 + o] = (a3[d] - mu) * rstd * ln2g[o] + ln2b[o];
    }

    // mm4: v = gelu(us @ ohW + ohb); LN3; out
    frag_zero(c);
    tail_mm(g_wtf + 12 * 8192, us, 132, 128, ws, c, st, ch, g, tg, t);
    frag_store(ms, 132, c, st, ch, g, tg);
    __syncthreads();
    float a4[32];
    sum = 0; sq = 0;
#pragma unroll
    for (int d = 0; d < 32; d++) {
        int o = cq * 32 + d;
        float v = gelu_exact(ms[nl * 132 + o] + ohb[o]);
        a4[d] = v;
        sum += v; sq += v * v;
    }
    sum = qsum(sum); sq = qsum(sq);
    mu = sum * (1.0f / 128.0f);
    rstd = rsqrtf(sq * (1.0f / 128.0f) - mu * mu + 1e-5f);

    float* op = out + ((size_t)b * NN + nb + nl) * 128 + cq * 32;
#pragma unroll
    for (int d4 = 0; d4 < 8; d4++) {
        float r0 = (a4[4 * d4 + 0] - mu) * rstd * ln3g[cq * 32 + 4 * d4 + 0] + ln3b[cq * 32 + 4 * d4 + 0];
        float r1 = (a4[4 * d4 + 1] - mu) * rstd * ln3g[cq * 32 + 4 * d4 + 1] + ln3b[cq * 32 + 4 * d4 + 1];
        float r2 = (a4[4 * d4 + 2] - mu) * rstd * ln3g[cq * 32 + 4 * d4 + 2] + ln3b[cq * 32 + 4 * d4 + 2];
        float r3 = (a4[4 * d4 + 3] - mu) * rstd * ln3g[cq * 32 + 4 * d4 + 3] + ln3b[cq * 32 + 4 * d4 + 3];
        ((float4*)op)[d4] = make_float4(r0, r1, r2, r3);
    }
}

// ------------------------- launch -------------------------
extern "C" void kernel_launch(void* const* d_in, const int* in_sizes, int n_in,
                              void* d_out, int out_size) {
    const float* x    = (const float*)d_in[0];
    const int*   grp  = (const int*)  d_in[1];
    const float* W0   = (const float*)d_in[2];
    const float* as0  = (const float*)d_in[3];
    const float* ad0  = (const float*)d_in[4];
    const float* W1   = (const float*)d_in[5];
    const float* as1  = (const float*)d_in[6];
    const float* ad1  = (const float*)d_in[7];
    const float* ln1g = (const float*)d_in[8];
    const float* ln1b = (const float*)d_in[9];
    const float* linW = (const float*)d_in[10];
    const float* linb = (const float*)d_in[11];
    const float* meW0 = (const float*)d_in[12];
    const float* meb0 = (const float*)d_in[13];
    const float* meW1 = (const float*)d_in[14];
    const float* meb1 = (const float*)d_in[15];
    const float* ln2g = (const float*)d_in[16];
    const float* ln2b = (const float*)d_in[17];
    const float* ohW  = (const float*)d_in[18];
    const float* ohb  = (const float*)d_in[19];
    const float* ln3g = (const float*)d_in[20];
    const float* ln3b = (const float*)d_in[21];
    float* out = (float*)d_out;

    cudaFuncSetAttribute(k_proj0, cudaFuncAttributeMaxDynamicSharedMemorySize, P0_SMEM);
    cudaFuncSetAttribute(k_attn0, cudaFuncAttributeMaxDynamicSharedMemorySize, A0_SMEM);
    cudaFuncSetAttribute(k_a1tail, cudaFuncAttributeMaxDynamicSharedMemorySize, A1T_SMEM);

    dim3 grid(NN / 64, BB);
    k_wprep<<<112, 256>>>(W0, W1, linW, meW0, meW1, ohW);
    k_proj0<<<grid, 256, P0_SMEM>>>(x, as0, ad0);
    k_attn0<<<grid, 256, A0_SMEM>>>(grp, as1, ad1);
    k_a1tail<<<grid, 256, A1T_SMEM>>>(x, ln1g, ln1b, linb, meb0, meb1,
                                      ln2g, ln2b, ohb, ln3g, ln3b, out);
}